// round 12
// baseline (speedup 1.0000x reference)
#include <cuda_runtime.h>
#include <cuda_fp16.h>
#include <math.h>

typedef unsigned long long u64;

#define NIMG 16
#define NO   192
#define Hh   160
#define Wd   160
#define HW   25600

#define KHKW3 2916
#define P3    9
#define A3    26244
#define U3IMG 1679616
#define KHKW5 1024
#define P5    25
#define A5    25600
#define U5IMG 1638400
#define NPI   560

// ---------------- scratch ----------------
__device__ __align__(16) __half g_ex[(size_t)NIMG*NO*HW];
__device__ __align__(16) __half g_u3[(size_t)NIMG*U3IMG];
__device__ __align__(16) __half g_u5[(size_t)NIMG*U5IMG];
__device__ __align__(16) float g_sf3[NIMG*P3*KHKW3];
__device__ __align__(16) float g_sf5[NIMG*P5*KHKW5];
__device__ float g_Z[NPI], g_S[NPI*64], g_Pm[NPI*64];
__device__ float g_gt[NPI*64], g_veff[NPI*64], g_beff[NPI];
__device__ __align__(16) float g_Wall[256*64];
__device__ __align__(16) uint4 g_WhA4[4*16*32];  // K6 HMMA A-fragments [mt][kt][lane]
__device__ __align__(16) uint4 g_WK1A4[12*4*32]; // K1 HMMA A-fragments [mt][kt][lane]
__device__ float g_vb[64];
__device__ __align__(16) float g_expWt[64*NO];

// ---------------- helpers ----------------
__device__ __forceinline__ float sigf(float x){ return 1.f/(1.f+expf(-x)); }
__device__ __forceinline__ int cover3(int h, int* r){
    int n=0;
    #pragma unroll
    for(int i=0;i<3;i++){ int lo=53*i; if(h>=lo && h<=lo+53) r[n++]=i; }
    return n;
}
__device__ __forceinline__ unsigned h2pack(float a, float b){
    __half2 h = __floats2half2_rn(a,b);
    return *(unsigned*)&h;
}

#define MMA16816(c0,c1,c2,c3,a,b0,b1) \
    asm volatile("mma.sync.aligned.m16n8k16.row.col.f32.f16.f16.f32 " \
        "{%0,%1,%2,%3},{%4,%5,%6,%7},{%8,%9},{%0,%1,%2,%3};" \
        : "+f"(c0),"+f"(c1),"+f"(c2),"+f"(c3) \
        : "r"((a).x),"r"((a).y),"r"((a).z),"r"((a).w),"r"(b0),"r"(b1))

// ================ K0a: zero accumulators ================
__global__ void k_zero(){
    int i = blockIdx.x*256 + threadIdx.x;
    if(i < NPI) g_Z[i]=0.f;
    if(i < NPI*64){ g_S[i]=0.f; g_Pm[i]=0.f; }
}

// ================ K0b: weight prep ================
__global__ void k_wprep(const float* __restrict__ exp_w, const float* __restrict__ res_w,
                        const float* __restrict__ res_b, const float* __restrict__ fus_w,
                        const float* __restrict__ fus_b){
    int t = threadIdx.x;
    for(int i=t;i<64*NO;i+=256){ int c=i/NO, o=i%NO; g_expWt[i]=exp_w[o*64+c]; }
    for(int i=t;i<NO*64;i+=256){
        int k=i/64, o=i%64; float s=0.f;
        for(int c=0;c<64;c++) s += fus_w[o*64+c]*res_w[c*NO+k];
        g_Wall[i]=s;
    }
    for(int i=t;i<64*64;i+=256){ int c=i/64, o=i%64; g_Wall[(192+c)*64+o]=fus_w[o*64+c]; }
    for(int o=t;o<64;o+=256){
        float s=fus_b[o];
        for(int c=0;c<64;c++) s += fus_w[o*64+c]*res_b[c];
        g_vb[o]=s;
    }
    __syncthreads();
    for(int i=t;i<2048;i+=256){
        int mt = i>>9, kt = (i>>5)&15, lane = i&31;
        int g = lane>>2, tig = lane&3;
        int k0 = kt*16, ob0 = mt*16;
        const float* W = g_Wall;
        unsigned r0 = h2pack(W[(k0+tig*2)*64+ob0+g],     W[(k0+tig*2+1)*64+ob0+g]);
        unsigned r1 = h2pack(W[(k0+tig*2)*64+ob0+g+8],   W[(k0+tig*2+1)*64+ob0+g+8]);
        unsigned r2 = h2pack(W[(k0+tig*2+8)*64+ob0+g],   W[(k0+tig*2+9)*64+ob0+g]);
        unsigned r3 = h2pack(W[(k0+tig*2+8)*64+ob0+g+8], W[(k0+tig*2+9)*64+ob0+g+8]);
        g_WhA4[i] = make_uint4(r0,r1,r2,r3);
    }
    for(int i=t;i<1536;i+=256){
        int mt = i>>7, kt = (i>>5)&3, lane = i&31;
        int g = lane>>2, tig = lane&3;
        int k0 = kt*16, ob0 = mt*16;
        const float* W = g_expWt;
        unsigned r0 = h2pack(W[(k0+tig*2)*NO+ob0+g],     W[(k0+tig*2+1)*NO+ob0+g]);
        unsigned r1 = h2pack(W[(k0+tig*2)*NO+ob0+g+8],   W[(k0+tig*2+1)*NO+ob0+g+8]);
        unsigned r2 = h2pack(W[(k0+tig*2+8)*NO+ob0+g],   W[(k0+tig*2+9)*NO+ob0+g]);
        unsigned r3 = h2pack(W[(k0+tig*2+8)*NO+ob0+g+8], W[(k0+tig*2+9)*NO+ob0+g+8]);
        g_WK1A4[i] = make_uint4(r0,r1,r2,r3);
    }
}

// ================ K1: HMMA ex = Wexp @ x + fused win1 stats ================
__global__ void __launch_bounds__(256) k1(const float* __restrict__ x,
                                          const float* __restrict__ exp_b,
                                          const float* __restrict__ wq,
                                          const float* __restrict__ wqb){
    __shared__ __align__(16) __half xh[32*72];
    __shared__ __align__(16) __half exsh[192*40];
    __shared__ float es[32];
    __shared__ float redP[256], redS[256];
    int t = threadIdx.x;
    int wt = blockIdx.x, h = blockIdx.y, n = blockIdx.z;
    int w0 = wt*32;

    const float* xp = x + (size_t)n*64*HW + (size_t)h*Wd + w0;
    for(int i=t;i<512;i+=256){
        int c=i>>3, p4=(i&7)*4;
        float4 v = *(const float4*)&xp[(size_t)c*HW + p4];
        xh[(p4  )*72 + c] = __float2half(v.x);
        xh[(p4+1)*72 + c] = __float2half(v.y);
        xh[(p4+2)*72 + c] = __float2half(v.z);
        xh[(p4+3)*72 + c] = __float2half(v.w);
    }
    __syncthreads();

    int lane = t&31, w = t>>5;
    int g = lane>>2, tig = lane&3;
    int mtb = (w&3)*3, nt0 = (w>>2)*2, nt1 = nt0+1;
    int px0 = nt0*8 + tig*2, px1 = nt1*8 + tig*2;

    const __half* b0base = &xh[(nt0*8+g)*72 + tig*2];
    const __half* b1base = &xh[(nt1*8+g)*72 + tig*2];
    unsigned bf0[8], bf1[8];
    #pragma unroll
    for(int kt=0;kt<4;kt++){
        bf0[kt*2  ] = *(const unsigned*)&b0base[kt*16];
        bf0[kt*2+1] = *(const unsigned*)&b0base[kt*16+8];
        bf1[kt*2  ] = *(const unsigned*)&b1base[kt*16];
        bf1[kt*2+1] = *(const unsigned*)&b1base[kt*16+8];
    }

    #pragma unroll
    for(int mi=0;mi<3;mi++){
        int mt = mtb+mi, ob0 = mt*16;
        float c00=0,c01=0,c02=0,c03=0, c10=0,c11=0,c12=0,c13=0;
        const uint4* wa = g_WK1A4 + mt*128 + lane;
        #pragma unroll
        for(int kt=0;kt<4;kt++){
            uint4 a = __ldg(&wa[kt*32]);
            MMA16816(c00,c01,c02,c03, a, bf0[kt*2],bf0[kt*2+1]);
            MMA16816(c10,c11,c12,c13, a, bf1[kt*2],bf1[kt*2+1]);
        }
        float b0 = __ldg(&exp_b[ob0+g]), b1 = __ldg(&exp_b[ob0+g+8]);
        *(unsigned*)&exsh[(ob0+g  )*40 + px0] = h2pack(c00+b0, c01+b0);
        *(unsigned*)&exsh[(ob0+g+8)*40 + px0] = h2pack(c02+b1, c03+b1);
        *(unsigned*)&exsh[(ob0+g  )*40 + px1] = h2pack(c10+b0, c11+b0);
        *(unsigned*)&exsh[(ob0+g+8)*40 + px1] = h2pack(c12+b1, c13+b1);
    }
    __syncthreads();

    // qdot (warp 0) overlaps the global store (other warps)
    if(t<32){
        float qd = wqb[0];
        #pragma unroll
        for(int c=0;c<64;c++) qd += wq[c]*__half2float(exsh[c*40+t]);
        float e = expf(qd);
        es[t]=e;
        float z=e;
        for(int off=16;off;off>>=1) z += __shfl_xor_sync(0xffffffffu,z,off);
        if(t==0) atomicAdd(&g_Z[n], z);
    }
    __half* exg = g_ex + (size_t)n*NO*HW + (size_t)h*Wd + w0;
    for(int i=t;i<768;i+=256){
        int r=i>>2, q=(i&3)*8;
        *(uint4*)&exg[(size_t)r*HW + q] = *(const uint4*)&exsh[r*40 + q];
    }
    __syncthreads();
    {   // S/Pm partials: all 256 threads (c = t&63, px-group = t>>6)
        int c=t&63, grp=t>>6;
        float Ps=0.f, Ss=0.f;
        #pragma unroll
        for(int px=grp*8; px<grp*8+8; px++){
            float v=__half2float(exsh[c*40+px]); Ps+=v; Ss+=v*es[px];
        }
        redP[t]=Ps; redS[t]=Ss;
    }
    __syncthreads();
    if(t<64){
        float Ps = redP[t]+redP[64+t]+redP[128+t]+redP[192+t];
        float Ss = redS[t]+redS[64+t]+redS[128+t]+redS[192+t];
        atomicAdd(&g_S[n*64+t], Ss);
        atomicAdd(&g_Pm[n*64+t], Ps);
    }
}

// ================ K2: repack into unfold order (warp-per-ci, fp16) ================
__global__ void __launch_bounds__(256) k2_5(){
    __shared__ __align__(16) __half rb[8][800];
    int y = blockIdx.x, n = blockIdx.y;
    int wp = threadIdx.x >> 5, lane = threadIdx.x & 31;
    for(int cit=0; cit<8; cit++){
        int ci = cit*8 + wp;
        const __half* src = g_ex + (size_t)n*NO*HW + (size_t)(128+ci)*HW;
        #pragma unroll
        for(int ph=0; ph<5; ph++){
            const __half2* row2 = (const __half2*)(src + (size_t)(ph*32+y)*Wd);
            #pragma unroll
            for(int it=0; it<3; it++){
                int idx = lane + it*32;
                if(idx<80){
                    __half2 v = row2[idx];
                    int w = idx*2, pw = w>>5, xx = w&31;
                    rb[wp][xx*25 + ph*5 + pw]     = __low2half(v);
                    rb[wp][(xx+1)*25 + ph*5 + pw] = __high2half(v);
                }
            }
        }
        __syncwarp();
        uint4* dst = (uint4*)(g_u5 + (size_t)n*U5IMG + (size_t)(ci*1024 + y*32)*25);
        const uint4* s = (const uint4*)rb[wp];
        #pragma unroll
        for(int it=0; it<4; it++){
            int k = lane + it*32;
            if(k < 100) dst[k] = s[k];
        }
        __syncwarp();
    }
}
__global__ void __launch_bounds__(256) k2_3(){
    __shared__ __align__(16) __half rb[8][488];
    int yy = blockIdx.x, n = blockIdx.y;
    int wp = threadIdx.x >> 5, lane = threadIdx.x & 31;
    for(int cit=0; cit<8; cit++){
        int ci = cit*8 + wp;
        const __half* src = g_ex + (size_t)n*NO*HW + (size_t)(64+ci)*HW;
        #pragma unroll
        for(int ph=0; ph<3; ph++){
            const __half2* row2 = (const __half2*)(src + (size_t)(53*ph+yy)*Wd);
            #pragma unroll
            for(int it=0; it<3; it++){
                int idx = lane + it*32;
                if(idx<80){
                    __half2 v = row2[idx];
                    int w0_ = idx*2;
                    __half hv[2] = {__low2half(v), __high2half(v)};
                    #pragma unroll
                    for(int hh=0; hh<2; hh++){
                        int w = w0_ + hh;
                        #pragma unroll
                        for(int pw=0; pw<3; pw++){
                            int xx = w - 53*pw;
                            if(xx>=0 && xx<54) rb[wp][xx*9 + ph*3 + pw] = hv[hh];
                        }
                    }
                }
            }
        }
        __syncwarp();
        unsigned* dst = (unsigned*)(g_u3 + (size_t)n*U3IMG + (size_t)ci*A3 + (size_t)yy*486);
        const unsigned* s = (const unsigned*)rb[wp];
        #pragma unroll
        for(int it=0; it<8; it++){
            int k = lane + it*32;
            if(k < 243) dst[k] = s[k];
        }
        __syncwarp();
    }
}

// ================ K3: fused stats (win3 + win5 in one launch) ================
__global__ void __launch_bounds__(256) k_stats(const float* __restrict__ wq,
                                               const float* __restrict__ wqb){
    __shared__ __half Vs[64*130];
    __shared__ float part[4*128];
    __shared__ float es[128];
    int lin = blockIdx.x, n = blockIdx.z;
    int t = threadIdx.x;
    const __half* base; int khkw, pi, q0;
    if(lin < 207){
        int bp = lin%9, qt = lin/9;
        khkw = KHKW3; q0 = qt*128;
        base = g_u3 + (size_t)n*U3IMG + (size_t)bp*64*KHKW3 + q0;
        pi = 16 + n*9 + bp;
    } else {
        lin -= 207;
        int bp = lin%25, qt = lin/25;
        khkw = KHKW5; q0 = qt*128;
        base = g_u5 + (size_t)n*U5IMG + (size_t)bp*64*KHKW5 + q0;
        pi = 160 + n*25 + bp;
    }
    int qlim = khkw - q0; if(qlim>128) qlim=128;

    for(int i=t;i<4096;i+=256){
        int c=i>>6, j2=i&63;
        unsigned v = 0;
        if(j2*2 < qlim) v = *(const unsigned*)&base[(size_t)c*khkw + j2*2];
        *(unsigned*)&Vs[c*130 + j2*2] = v;
    }
    __syncthreads();
    {
        int j2=t&63, cg=t>>6;
        float sx=0.f, sy=0.f;
        #pragma unroll 8
        for(int cc=cg*16; cc<cg*16+16; cc++){
            float2 f = __half22float2(*(const __half2*)&Vs[cc*130 + j2*2]);
            float w = wq[cc];
            sx += w*f.x; sy += w*f.y;
        }
        part[cg*128 + j2*2]   = sx;
        part[cg*128 + j2*2+1] = sy;
    }
    __syncthreads();
    if(t<128){
        float qd = part[t]+part[128+t]+part[256+t]+part[384+t] + wqb[0];
        float e = (t<qlim) ? expf(qd) : 0.f;
        es[t]=e;
        float z=e;
        for(int off=16;off;off>>=1) z += __shfl_xor_sync(0xffffffffu,z,off);
        if((t&31)==0) atomicAdd(&g_Z[pi], z);
    }
    __syncthreads();
    {
        int c=t&63, jg=t>>6;
        float ss=0.f, pm=0.f;
        #pragma unroll 8
        for(int j2=jg*16; j2<jg*16+16; j2++){
            float2 f = __half22float2(*(const __half2*)&Vs[c*130 + j2*2]);
            ss += f.x*es[2*j2] + f.y*es[2*j2+1];
            pm += f.x + f.y;
        }
        atomicAdd(&g_S[pi*64+c], ss);
        atomicAdd(&g_Pm[pi*64+c], pm);
    }
}

// ================ K4: per-pseudo-image finalize ================
__global__ void __launch_bounds__(64) k4(const float* __restrict__ chwv_w, const float* __restrict__ chwv_b,
                                         const float* __restrict__ chwz_w, const float* __restrict__ chwz_b,
                                         const float* __restrict__ ln_g,  const float* __restrict__ ln_b,
                                         const float* __restrict__ spwq_w,const float* __restrict__ spwq_b,
                                         const float* __restrict__ spwv_w,const float* __restrict__ spwv_b){
    int p = blockIdx.x, t = threadIdx.x;
    float hw = (p<16) ? 25600.f : ((p<160) ? 2916.f : 1024.f);
    __shared__ float xbar[64], pmean[64], wz[32], red[64], swq[32];

    float Zinv = 1.f/g_Z[p];
    xbar[t]  = g_S[p*64+t]*Zinv;
    pmean[t] = g_Pm[p*64+t]/hw;
    __syncthreads();

    if(t<32){
        float s = chwv_b[t];
        for(int c=0;c<64;c++) s += chwv_w[t*64+c]*xbar[c];
        wz[t]=s;
    }
    __syncthreads();

    float z = chwz_b[t];
    for(int j=0;j<32;j++) z += chwz_w[t*32+j]*wz[j];

    red[t]=z; __syncthreads();
    for(int s=32;s>0;s>>=1){ if(t<s) red[t]+=red[t+s]; __syncthreads(); }
    float mu = red[0]*(1.f/64.f); __syncthreads();
    float d = z-mu;
    red[t]=d*d; __syncthreads();
    for(int s=32;s>0;s>>=1){ if(t<s) red[t]+=red[t+s]; __syncthreads(); }
    float var = red[0]*(1.f/64.f);

    float zn = d*rsqrtf(var+1e-5f)*ln_g[t] + ln_b[t];
    g_gt[p*64+t] = sigf(zn);
    __syncthreads();

    if(t<32){
        float s = spwq_b[t];
        for(int c=0;c<64;c++) s += spwq_w[t*64+c]*pmean[c];
        float m=s;
        for(int off=16;off;off>>=1) m=fmaxf(m,__shfl_xor_sync(0xffffffffu,m,off));
        float e=expf(s-m), sum=e;
        for(int off=16;off;off>>=1) sum+=__shfl_xor_sync(0xffffffffu,sum,off);
        swq[t]=e/sum;
    }
    __syncthreads();

    float v=0.f;
    for(int j=0;j<32;j++) v += swq[j]*spwv_w[j*64+t];
    g_veff[p*64+t]=v;
    if(t==0){
        float b=0.f;
        for(int j=0;j<32;j++) b += swq[j]*spwv_b[j];
        g_beff[p]=b;
    }
}

// ================ K5: fused s-field (win3 + win5 in one launch) ================
__global__ void __launch_bounds__(256) k_sfield(){
    __shared__ __half Vs[64*130];
    __shared__ float part[4*128];
    __shared__ float ve[64];
    int lin = blockIdx.x, n = blockIdx.z;
    int t = threadIdx.x;
    const __half* base; float* sf; int khkw, pi, q0;
    if(lin < 207){
        int bp = lin%9, qt = lin/9;
        khkw = KHKW3; q0 = qt*128;
        base = g_u3 + (size_t)n*U3IMG + (size_t)bp*64*KHKW3 + q0;
        sf = g_sf3 + n*A3 + bp*KHKW3;
        pi = 16 + n*9 + bp;
    } else {
        lin -= 207;
        int bp = lin%25, qt = lin/25;
        khkw = KHKW5; q0 = qt*128;
        base = g_u5 + (size_t)n*U5IMG + (size_t)bp*64*KHKW5 + q0;
        sf = g_sf5 + n*25600 + bp*1024;
        pi = 160 + n*25 + bp;
    }
    int qlim = khkw - q0; if(qlim>128) qlim=128;

    if(t<64) ve[t]=g_veff[pi*64+t];
    for(int i=t;i<4096;i+=256){
        int c=i>>6, j2=i&63;
        unsigned v = 0;
        if(j2*2 < qlim) v = *(const unsigned*)&base[(size_t)c*khkw + j2*2];
        *(unsigned*)&Vs[c*130 + j2*2] = v;
    }
    __syncthreads();
    {
        int j2=t&63, cg=t>>6;
        float sx=0.f, sy=0.f;
        #pragma unroll 8
        for(int cc=cg*16; cc<cg*16+16; cc++){
            float2 f = __half22float2(*(const __half2*)&Vs[cc*130 + j2*2]);
            float w = ve[cc];
            sx += w*f.x; sy += w*f.y;
        }
        part[cg*128 + j2*2]   = sx;
        part[cg*128 + j2*2+1] = sy;
    }
    __syncthreads();
    if(t<128 && t<qlim){
        float sd = part[t]+part[128+t]+part[256+t]+part[384+t] + g_beff[pi];
        sf[q0 + t] = sigf(sd);
    }
}

// ================ K6: 64-px tiles, vsh multiplier + HMMA GEMM ================
__global__ void __launch_bounds__(256) k6(const float* __restrict__ x, float* __restrict__ out){
    __shared__ __align__(16) __half vsh[64*264];     // [px][k], rows 192..255 = x
    __shared__ float s1s[64], icntS[64];
    __shared__ int q5s[64], cp05s[64];
    __shared__ int q3s[4][64], cp03s[4][64];
    __shared__ int nsegS[64];

    int t = threadIdx.x;
    int wt = blockIdx.x, hb = blockIdx.y, n = blockIdx.z;
    int w0 = wt*32, h0 = hb*2;

    // ex tile (192k x 64px over 2 rows) -> vsh
    const __half* exg = g_ex + (size_t)n*NO*HW + (size_t)h0*Wd + w0;
    for(int i=t;i<1536;i+=256){
        int k=i>>3, px8=(i&7)*8;
        int r=px8>>5, col=px8&31;
        uint4 raw = *(const uint4*)&exg[(size_t)k*HW + r*Wd + col];
        const __half* hp = (const __half*)&raw;
        #pragma unroll
        for(int j=0;j<8;j++) vsh[(px8+j)*264 + k] = hp[j];
    }
    // x -> vsh rows 192..255
    const float* xp = x + (size_t)n*64*HW + (size_t)h0*Wd + w0;
    for(int i=t;i<1024;i+=256){
        int c=i>>4, p4=(i&15)*4;
        int r=p4>>5, col=p4&31;
        float4 v = *(const float4*)&xp[(size_t)c*HW + r*Wd + col];
        vsh[(p4  )*264 + 192 + c] = __float2half(v.x);
        vsh[(p4+1)*264 + 192 + c] = __float2half(v.y);
        vsh[(p4+2)*264 + 192 + c] = __float2half(v.z);
        vsh[(p4+3)*264 + 192 + c] = __float2half(v.w);
    }
    if(t<64){
        int h = h0 + (t>>5), w = w0 + (t&31);
        int rp5 = ((h&31)*32 + (w&31))*P5 + (h>>5)*5 + (w>>5);
        q5s[t] = rp5 & 1023; cp05s[t] = rp5 >> 10;
        int R[2], C[2];
        int nr = cover3(h, R), nc = cover3(w, C);
        nsegS[t] = nr*nc;
        icntS[t] = 1.f/(float)(nr*nc);
        for(int ri=0;ri<nr;ri++)
            for(int cj=0;cj<nc;cj++){
                int ph=R[ri], pw=C[cj];
                int rp3 = ((h-53*ph)*54 + (w-53*pw))*P3 + ph*3 + pw;
                int s = ri*nc + cj;
                cp03s[s][t] = rp3 / KHKW3;
                q3s[s][t]   = rp3 % KHKW3;
            }
    }
    __syncthreads();

    // win1 s-field from vsh chunk0 (unscaled)
    if(t<64){
        float sd = g_beff[n];
        const float* ve = &g_veff[n*64];
        #pragma unroll
        for(int c=0;c<64;c++) sd += ve[c]*__half2float(vsh[t*264+c]);
        s1s[t] = sigf(sd);
    }
    __syncthreads();

    // multiplier: 96 k-pairs x 64 px; lane -> k-pair within chunk (conflict-free)
    {
        int lane = t&31, wp = t>>5;
        int ci0 = lane*2;
        #pragma unroll
        for(int j=0;j<24;j++){
            int idx = wp + j*8;           // 0..191 = (chunk g32, pix)
            int g32 = idx>>6, pix = idx&63;
            int k = (g32<<6) + ci0;
            __half2* cell = (__half2*)&vsh[pix*264 + k];
            float2 exv = __half22float2(*cell);
            float m0, m1;
            if(g32==0){
                float s1 = s1s[pix];
                m0 = g_gt[n*64+ci0  ] + s1;
                m1 = g_gt[n*64+ci0+1] + s1;
            } else if(g32==2){
                int q5 = q5s[pix];
                int cpv0 = cp05s[pix] + 25*ci0;
                int cpv1 = cpv0 + 25;
                int bp0=cpv0>>6, cp0=cpv0&63, bp1=cpv1>>6, cp1=cpv1&63;
                m0 = g_gt[(160+n*25+bp0)*64+cp0] + g_sf5[n*25600 + (bp0<<10) + q5];
                m1 = g_gt[(160+n*25+bp1)*64+cp1] + g_sf5[n*25600 + (bp1<<10) + q5];
            } else {
                m0 = 0.f; m1 = 0.f;
                int ns = nsegS[pix];
                #pragma unroll
                for(int s=0;s<4;s++){
                    if(s>=ns) break;
                    int q3 = q3s[s][pix];
                    int cpv0 = cp03s[s][pix] + 9*ci0;
                    int cpv1 = cpv0 + 9;
                    int bp0=cpv0>>6, cp0=cpv0&63, bp1=cpv1>>6, cp1=cpv1&63;
                    m0 += g_gt[(16+n*9+bp0)*64+cp0] + g_sf3[n*A3 + bp0*KHKW3 + q3];
                    m1 += g_gt[(16+n*9+bp1)*64+cp1] + g_sf3[n*A3 + bp1*KHKW3 + q3];
                }
                float ic = icntS[pix];
                m0 *= ic; m1 *= ic;
            }
            exv.x *= (1.f + m0);
            exv.y *= (1.f + m1);
            *cell = __floats2half2_rn(exv.x, exv.y);
        }
    }
    __syncthreads();

    // HMMA GEMM: out[64ob][64px] = Wall^T[64][256] @ vsh[256][64]
    int lane = t&31, w = t>>5;
    int g = lane>>2, tig = lane&3;
    int mt = w&3, ntg = w>>2;        // ntg in {0,1} -> nt = ntg*4 + 0..3
    int ob0 = mt*16;

    float vb0 = __ldg(&g_vb[ob0+g]), vb1 = __ldg(&g_vb[ob0+g+8]);
    float acc[4][4];
    #pragma unroll
    for(int j=0;j<4;j++){ acc[j][0]=vb0; acc[j][1]=vb0; acc[j][2]=vb1; acc[j][3]=vb1; }

    const uint4* wa = g_WhA4 + mt*512 + lane;
    const __half* bb[4];
    #pragma unroll
    for(int j=0;j<4;j++) bb[j] = &vsh[((ntg*4+j)*8+g)*264 + tig*2];

    #pragma unroll
    for(int kt=0;kt<16;kt++){
        uint4 a = __ldg(&wa[kt*32]);
        int k0 = kt*16;
        #pragma unroll
        for(int j=0;j<4;j++){
            unsigned p0 = *(const unsigned*)&bb[j][k0];
            unsigned p1 = *(const unsigned*)&bb[j][k0+8];
            MMA16816(acc[j][0],acc[j][1],acc[j][2],acc[j][3], a, p0,p1);
        }
    }

    float* og = out + (size_t)n*64*HW + (size_t)h0*Wd + w0;
    #pragma unroll
    for(int j=0;j<4;j++){
        int px0 = (ntg*4+j)*8 + tig*2;
        int r = px0>>5, col = px0&31;
        *(float2*)&og[(size_t)(ob0+g  )*HW + r*Wd + col] = make_float2(acc[j][0],acc[j][1]);
        *(float2*)&og[(size_t)(ob0+g+8)*HW + r*Wd + col] = make_float2(acc[j][2],acc[j][3]);
    }
}

// ================ launch ================
extern "C" void kernel_launch(void* const* d_in, const int* in_sizes, int n_in,
                              void* d_out, int out_size){
    const float* x      = (const float*)d_in[0];
    const float* exp_w  = (const float*)d_in[1];
    const float* exp_b  = (const float*)d_in[2];
    const float* res_w  = (const float*)d_in[3];
    const float* res_b  = (const float*)d_in[4];
    const float* fus_w  = (const float*)d_in[5];
    const float* fus_b  = (const float*)d_in[6];
    const float* chwv_w = (const float*)d_in[7];
    const float* chwv_b = (const float*)d_in[8];
    const float* chwq_w = (const float*)d_in[9];
    const float* chwq_b = (const float*)d_in[10];
    const float* chwz_w = (const float*)d_in[11];
    const float* chwz_b = (const float*)d_in[12];
    const float* ln_g   = (const float*)d_in[13];
    const float* ln_b   = (const float*)d_in[14];
    const float* spwv_w = (const float*)d_in[15];
    const float* spwv_b = (const float*)d_in[16];
    const float* spwq_w = (const float*)d_in[17];
    const float* spwq_b = (const float*)d_in[18];
    float* out = (float*)d_out;

    k_zero<<<(NPI*64+255)/256, 256>>>();
    k_wprep<<<1, 256>>>(exp_w, res_w, res_b, fus_w, fus_b);

    k1<<<dim3(Wd/32, Hh, NIMG), 256>>>(x, exp_b, chwq_w, chwq_b);

    k2_5<<<dim3(32,NIMG), 256>>>();
    k2_3<<<dim3(54,NIMG), 256>>>();

    k_stats<<<dim3(407, 1, NIMG), 256>>>(chwq_w, chwq_b);

    k4<<<NPI, 64>>>(chwv_w, chwv_b, chwz_w, chwz_b, ln_g, ln_b,
                    spwq_w, spwq_b, spwv_w, spwv_b);

    k_sfield<<<dim3(407, 1, NIMG), 256>>>();

    k6<<<dim3(Wd/32, Hh/2, NIMG), 256>>>(x, out);
}

// round 14
// speedup vs baseline: 1.1421x; 1.1421x over previous
#include <cuda_runtime.h>
#include <cuda_fp16.h>
#include <math.h>

typedef unsigned long long u64;

#define NIMG 16
#define NO   192
#define Hh   160
#define Wd   160
#define HW   25600

#define KHKW3 2916
#define P3    9
#define A3    26244
#define U3IMG 1679616
#define KHKW5 1024
#define P5    25
#define A5    25600
#define U5IMG 1638400
#define NPI   560

// ---------------- scratch ----------------
__device__ __align__(16) __half g_ex[(size_t)NIMG*NO*HW];
__device__ __align__(16) __half g_u3[(size_t)NIMG*U3IMG];
__device__ __align__(16) __half g_u5[(size_t)NIMG*U5IMG];
__device__ __align__(16) float g_sf3[NIMG*P3*KHKW3];
__device__ __align__(16) float g_sf5[NIMG*P5*KHKW5];
__device__ float g_Z[NPI], g_S[NPI*64], g_Pm[NPI*64];
__device__ float g_gt[NPI*64], g_veff[NPI*64], g_beff[NPI];
__device__ __align__(16) float g_Wall[256*64];
__device__ __align__(16) uint4 g_WhA4[4*16*32];  // K6 HMMA A-fragments [mt][kt][lane]
__device__ __align__(16) uint4 g_WK1A4[12*4*32]; // K1 HMMA A-fragments [mt][kt][lane]
__device__ float g_vb[64];
__device__ __align__(16) float g_expWt[64*NO];

// ---------------- helpers ----------------
__device__ __forceinline__ float sigf(float x){ return 1.f/(1.f+expf(-x)); }
__device__ __forceinline__ int cover3(int h, int* r){
    int n=0;
    #pragma unroll
    for(int i=0;i<3;i++){ int lo=53*i; if(h>=lo && h<=lo+53) r[n++]=i; }
    return n;
}
__device__ __forceinline__ unsigned h2pack(float a, float b){
    __half2 h = __floats2half2_rn(a,b);
    return *(unsigned*)&h;
}

#define MMA16816(c0,c1,c2,c3,a,b0,b1) \
    asm volatile("mma.sync.aligned.m16n8k16.row.col.f32.f16.f16.f32 " \
        "{%0,%1,%2,%3},{%4,%5,%6,%7},{%8,%9},{%0,%1,%2,%3};" \
        : "+f"(c0),"+f"(c1),"+f"(c2),"+f"(c3) \
        : "r"((a).x),"r"((a).y),"r"((a).z),"r"((a).w),"r"(b0),"r"(b1))

// ================ K0a: zero accumulators ================
__global__ void k_zero(){
    int i = blockIdx.x*256 + threadIdx.x;
    if(i < NPI) g_Z[i]=0.f;
    if(i < NPI*64){ g_S[i]=0.f; g_Pm[i]=0.f; }
}

// ================ K0b: weight prep ================
__global__ void k_wprep(const float* __restrict__ exp_w, const float* __restrict__ res_w,
                        const float* __restrict__ res_b, const float* __restrict__ fus_w,
                        const float* __restrict__ fus_b){
    int t = threadIdx.x;
    for(int i=t;i<64*NO;i+=256){ int c=i/NO, o=i%NO; g_expWt[i]=exp_w[o*64+c]; }
    for(int i=t;i<NO*64;i+=256){
        int k=i/64, o=i%64; float s=0.f;
        for(int c=0;c<64;c++) s += fus_w[o*64+c]*res_w[c*NO+k];
        g_Wall[i]=s;
    }
    for(int i=t;i<64*64;i+=256){ int c=i/64, o=i%64; g_Wall[(192+c)*64+o]=fus_w[o*64+c]; }
    for(int o=t;o<64;o+=256){
        float s=fus_b[o];
        for(int c=0;c<64;c++) s += fus_w[o*64+c]*res_b[c];
        g_vb[o]=s;
    }
    __syncthreads();
    for(int i=t;i<2048;i+=256){
        int mt = i>>9, kt = (i>>5)&15, lane = i&31;
        int g = lane>>2, tig = lane&3;
        int k0 = kt*16, ob0 = mt*16;
        const float* W = g_Wall;
        unsigned r0 = h2pack(W[(k0+tig*2)*64+ob0+g],     W[(k0+tig*2+1)*64+ob0+g]);
        unsigned r1 = h2pack(W[(k0+tig*2)*64+ob0+g+8],   W[(k0+tig*2+1)*64+ob0+g+8]);
        unsigned r2 = h2pack(W[(k0+tig*2+8)*64+ob0+g],   W[(k0+tig*2+9)*64+ob0+g]);
        unsigned r3 = h2pack(W[(k0+tig*2+8)*64+ob0+g+8], W[(k0+tig*2+9)*64+ob0+g+8]);
        g_WhA4[i] = make_uint4(r0,r1,r2,r3);
    }
    for(int i=t;i<1536;i+=256){
        int mt = i>>7, kt = (i>>5)&3, lane = i&31;
        int g = lane>>2, tig = lane&3;
        int k0 = kt*16, ob0 = mt*16;
        const float* W = g_expWt;
        unsigned r0 = h2pack(W[(k0+tig*2)*NO+ob0+g],     W[(k0+tig*2+1)*NO+ob0+g]);
        unsigned r1 = h2pack(W[(k0+tig*2)*NO+ob0+g+8],   W[(k0+tig*2+1)*NO+ob0+g+8]);
        unsigned r2 = h2pack(W[(k0+tig*2+8)*NO+ob0+g],   W[(k0+tig*2+9)*NO+ob0+g]);
        unsigned r3 = h2pack(W[(k0+tig*2+8)*NO+ob0+g+8], W[(k0+tig*2+9)*NO+ob0+g+8]);
        g_WK1A4[i] = make_uint4(r0,r1,r2,r3);
    }
}

// ================ K1: HMMA ex = Wexp @ x + fused win1 stats (R11) ================
__global__ void __launch_bounds__(256) k1(const float* __restrict__ x,
                                          const float* __restrict__ exp_b,
                                          const float* __restrict__ wq,
                                          const float* __restrict__ wqb){
    __shared__ __align__(16) __half xh[32*72];     // [px][c], pitch 72 halves
    __shared__ __align__(16) __half exsh[192*40];  // [ob][px], pitch 40 halves
    __shared__ float es[32];
    int t = threadIdx.x;
    int wt = blockIdx.x, h = blockIdx.y, n = blockIdx.z;
    int w0 = wt*32;

    const float* xp = x + (size_t)n*64*HW + (size_t)h*Wd + w0;
    for(int i=t;i<512;i+=256){
        int c=i>>3, p4=(i&7)*4;
        float4 v = *(const float4*)&xp[(size_t)c*HW + p4];
        xh[(p4  )*72 + c] = __float2half(v.x);
        xh[(p4+1)*72 + c] = __float2half(v.y);
        xh[(p4+2)*72 + c] = __float2half(v.z);
        xh[(p4+3)*72 + c] = __float2half(v.w);
    }
    __syncthreads();

    int lane = t&31, w = t>>5;
    int g = lane>>2, tig = lane&3;
    int mtb = (w&3)*3, nt0 = (w>>2)*2, nt1 = nt0+1;
    int px0 = nt0*8 + tig*2, px1 = nt1*8 + tig*2;

    const __half* b0base = &xh[(nt0*8+g)*72 + tig*2];
    const __half* b1base = &xh[(nt1*8+g)*72 + tig*2];
    unsigned bf0[8], bf1[8];
    #pragma unroll
    for(int kt=0;kt<4;kt++){
        bf0[kt*2  ] = *(const unsigned*)&b0base[kt*16];
        bf0[kt*2+1] = *(const unsigned*)&b0base[kt*16+8];
        bf1[kt*2  ] = *(const unsigned*)&b1base[kt*16];
        bf1[kt*2+1] = *(const unsigned*)&b1base[kt*16+8];
    }

    #pragma unroll
    for(int mi=0;mi<3;mi++){
        int mt = mtb+mi, ob0 = mt*16;
        float c00=0,c01=0,c02=0,c03=0, c10=0,c11=0,c12=0,c13=0;
        const uint4* wa = g_WK1A4 + mt*128 + lane;
        #pragma unroll
        for(int kt=0;kt<4;kt++){
            uint4 a = __ldg(&wa[kt*32]);
            MMA16816(c00,c01,c02,c03, a, bf0[kt*2],bf0[kt*2+1]);
            MMA16816(c10,c11,c12,c13, a, bf1[kt*2],bf1[kt*2+1]);
        }
        float b0 = __ldg(&exp_b[ob0+g]), b1 = __ldg(&exp_b[ob0+g+8]);
        *(unsigned*)&exsh[(ob0+g  )*40 + px0] = h2pack(c00+b0, c01+b0);
        *(unsigned*)&exsh[(ob0+g+8)*40 + px0] = h2pack(c02+b1, c03+b1);
        *(unsigned*)&exsh[(ob0+g  )*40 + px1] = h2pack(c10+b0, c11+b0);
        *(unsigned*)&exsh[(ob0+g+8)*40 + px1] = h2pack(c12+b1, c13+b1);
    }
    __syncthreads();

    __half* exg = g_ex + (size_t)n*NO*HW + (size_t)h*Wd + w0;
    for(int i=t;i<768;i+=256){
        int r=i>>2, q=(i&3)*8;
        *(uint4*)&exg[(size_t)r*HW + q] = *(const uint4*)&exsh[r*40 + q];
    }

    if(t<32){
        float qd = wqb[0];
        #pragma unroll
        for(int c=0;c<64;c++) qd += wq[c]*__half2float(exsh[c*40+t]);
        float e = expf(qd);
        es[t]=e;
        float z=e;
        for(int off=16;off;off>>=1) z += __shfl_xor_sync(0xffffffffu,z,off);
        if(t==0) atomicAdd(&g_Z[n], z);
    }
    __syncthreads();
    if(t<64){
        float Ps=0.f, Ss=0.f;
        #pragma unroll
        for(int px=0;px<32;px++){ float v=__half2float(exsh[t*40+px]); Ps+=v; Ss+=v*es[px]; }
        atomicAdd(&g_S[n*64+t], Ss);
        atomicAdd(&g_Pm[n*64+t], Ps);
    }
}

// ================ K2: repack into unfold order (warp-per-ci, fp16) ================
__global__ void __launch_bounds__(256) k2_5(){
    __shared__ __align__(16) __half rb[8][800];
    int y = blockIdx.x, n = blockIdx.y;
    int wp = threadIdx.x >> 5, lane = threadIdx.x & 31;
    for(int cit=0; cit<8; cit++){
        int ci = cit*8 + wp;
        const __half* src = g_ex + (size_t)n*NO*HW + (size_t)(128+ci)*HW;
        #pragma unroll
        for(int ph=0; ph<5; ph++){
            const __half2* row2 = (const __half2*)(src + (size_t)(ph*32+y)*Wd);
            #pragma unroll
            for(int it=0; it<3; it++){
                int idx = lane + it*32;
                if(idx<80){
                    __half2 v = row2[idx];
                    int w = idx*2, pw = w>>5, xx = w&31;
                    rb[wp][xx*25 + ph*5 + pw]     = __low2half(v);
                    rb[wp][(xx+1)*25 + ph*5 + pw] = __high2half(v);
                }
            }
        }
        __syncwarp();
        uint4* dst = (uint4*)(g_u5 + (size_t)n*U5IMG + (size_t)(ci*1024 + y*32)*25);
        const uint4* s = (const uint4*)rb[wp];
        #pragma unroll
        for(int it=0; it<4; it++){
            int k = lane + it*32;
            if(k < 100) dst[k] = s[k];
        }
        __syncwarp();
    }
}
__global__ void __launch_bounds__(256) k2_3(){
    __shared__ __align__(16) __half rb[8][488];
    int yy = blockIdx.x, n = blockIdx.y;
    int wp = threadIdx.x >> 5, lane = threadIdx.x & 31;
    for(int cit=0; cit<8; cit++){
        int ci = cit*8 + wp;
        const __half* src = g_ex + (size_t)n*NO*HW + (size_t)(64+ci)*HW;
        #pragma unroll
        for(int ph=0; ph<3; ph++){
            const __half2* row2 = (const __half2*)(src + (size_t)(53*ph+yy)*Wd);
            #pragma unroll
            for(int it=0; it<3; it++){
                int idx = lane + it*32;
                if(idx<80){
                    __half2 v = row2[idx];
                    int w0_ = idx*2;
                    __half hv[2] = {__low2half(v), __high2half(v)};
                    #pragma unroll
                    for(int hh=0; hh<2; hh++){
                        int w = w0_ + hh;
                        #pragma unroll
                        for(int pw=0; pw<3; pw++){
                            int xx = w - 53*pw;
                            if(xx>=0 && xx<54) rb[wp][xx*9 + ph*3 + pw] = hv[hh];
                        }
                    }
                }
            }
        }
        __syncwarp();
        unsigned* dst = (unsigned*)(g_u3 + (size_t)n*U3IMG + (size_t)ci*A3 + (size_t)yy*486);
        const unsigned* s = (const unsigned*)rb[wp];
        #pragma unroll
        for(int it=0; it<8; it++){
            int k = lane + it*32;
            if(k < 243) dst[k] = s[k];
        }
        __syncwarp();
    }
}

// ================ K3: fused stats (win3 + win5 in one launch) ================
__global__ void __launch_bounds__(256) k_stats(const float* __restrict__ wq,
                                               const float* __restrict__ wqb){
    __shared__ __half Vs[64*130];
    __shared__ float part[4*128];
    __shared__ float es[128];
    int lin = blockIdx.x, n = blockIdx.z;
    int t = threadIdx.x;
    const __half* base; int khkw, pi, q0;
    if(lin < 207){
        int bp = lin%9, qt = lin/9;
        khkw = KHKW3; q0 = qt*128;
        base = g_u3 + (size_t)n*U3IMG + (size_t)bp*64*KHKW3 + q0;
        pi = 16 + n*9 + bp;
    } else {
        lin -= 207;
        int bp = lin%25, qt = lin/25;
        khkw = KHKW5; q0 = qt*128;
        base = g_u5 + (size_t)n*U5IMG + (size_t)bp*64*KHKW5 + q0;
        pi = 160 + n*25 + bp;
    }
    int qlim = khkw - q0; if(qlim>128) qlim=128;

    for(int i=t;i<4096;i+=256){
        int c=i>>6, j2=i&63;
        unsigned v = 0;
        if(j2*2 < qlim) v = *(const unsigned*)&base[(size_t)c*khkw + j2*2];
        *(unsigned*)&Vs[c*130 + j2*2] = v;
    }
    __syncthreads();
    {
        int j2=t&63, cg=t>>6;
        float sx=0.f, sy=0.f;
        #pragma unroll 8
        for(int cc=cg*16; cc<cg*16+16; cc++){
            float2 f = __half22float2(*(const __half2*)&Vs[cc*130 + j2*2]);
            float w = wq[cc];
            sx += w*f.x; sy += w*f.y;
        }
        part[cg*128 + j2*2]   = sx;
        part[cg*128 + j2*2+1] = sy;
    }
    __syncthreads();
    if(t<128){
        float qd = part[t]+part[128+t]+part[256+t]+part[384+t] + wqb[0];
        float e = (t<qlim) ? expf(qd) : 0.f;
        es[t]=e;
        float z=e;
        for(int off=16;off;off>>=1) z += __shfl_xor_sync(0xffffffffu,z,off);
        if((t&31)==0) atomicAdd(&g_Z[pi], z);
    }
    __syncthreads();
    {
        int c=t&63, jg=t>>6;
        float ss=0.f, pm=0.f;
        #pragma unroll 8
        for(int j2=jg*16; j2<jg*16+16; j2++){
            float2 f = __half22float2(*(const __half2*)&Vs[c*130 + j2*2]);
            ss += f.x*es[2*j2] + f.y*es[2*j2+1];
            pm += f.x + f.y;
        }
        atomicAdd(&g_S[pi*64+c], ss);
        atomicAdd(&g_Pm[pi*64+c], pm);
    }
}

// ================ K4: per-pseudo-image finalize ================
__global__ void __launch_bounds__(64) k4(const float* __restrict__ chwv_w, const float* __restrict__ chwv_b,
                                         const float* __restrict__ chwz_w, const float* __restrict__ chwz_b,
                                         const float* __restrict__ ln_g,  const float* __restrict__ ln_b,
                                         const float* __restrict__ spwq_w,const float* __restrict__ spwq_b,
                                         const float* __restrict__ spwv_w,const float* __restrict__ spwv_b){
    int p = blockIdx.x, t = threadIdx.x;
    float hw = (p<16) ? 25600.f : ((p<160) ? 2916.f : 1024.f);
    __shared__ float xbar[64], pmean[64], wz[32], red[64], swq[32];

    float Zinv = 1.f/g_Z[p];
    xbar[t]  = g_S[p*64+t]*Zinv;
    pmean[t] = g_Pm[p*64+t]/hw;
    __syncthreads();

    if(t<32){
        float s = chwv_b[t];
        for(int c=0;c<64;c++) s += chwv_w[t*64+c]*xbar[c];
        wz[t]=s;
    }
    __syncthreads();

    float z = chwz_b[t];
    for(int j=0;j<32;j++) z += chwz_w[t*32+j]*wz[j];

    red[t]=z; __syncthreads();
    for(int s=32;s>0;s>>=1){ if(t<s) red[t]+=red[t+s]; __syncthreads(); }
    float mu = red[0]*(1.f/64.f); __syncthreads();
    float d = z-mu;
    red[t]=d*d; __syncthreads();
    for(int s=32;s>0;s>>=1){ if(t<s) red[t]+=red[t+s]; __syncthreads(); }
    float var = red[0]*(1.f/64.f);

    float zn = d*rsqrtf(var+1e-5f)*ln_g[t] + ln_b[t];
    g_gt[p*64+t] = sigf(zn);
    __syncthreads();

    if(t<32){
        float s = spwq_b[t];
        for(int c=0;c<64;c++) s += spwq_w[t*64+c]*pmean[c];
        float m=s;
        for(int off=16;off;off>>=1) m=fmaxf(m,__shfl_xor_sync(0xffffffffu,m,off));
        float e=expf(s-m), sum=e;
        for(int off=16;off;off>>=1) sum+=__shfl_xor_sync(0xffffffffu,sum,off);
        swq[t]=e/sum;
    }
    __syncthreads();

    float v=0.f;
    for(int j=0;j<32;j++) v += swq[j]*spwv_w[j*64+t];
    g_veff[p*64+t]=v;
    if(t==0){
        float b=0.f;
        for(int j=0;j<32;j++) b += swq[j]*spwv_b[j];
        g_beff[p]=b;
    }
}

// ================ K5: fused s-field (win3 + win5 in one launch) ================
__global__ void __launch_bounds__(256) k_sfield(){
    __shared__ __half Vs[64*130];
    __shared__ float part[4*128];
    __shared__ float ve[64];
    int lin = blockIdx.x, n = blockIdx.z;
    int t = threadIdx.x;
    const __half* base; float* sf; int khkw, pi, q0;
    if(lin < 207){
        int bp = lin%9, qt = lin/9;
        khkw = KHKW3; q0 = qt*128;
        base = g_u3 + (size_t)n*U3IMG + (size_t)bp*64*KHKW3 + q0;
        sf = g_sf3 + n*A3 + bp*KHKW3;
        pi = 16 + n*9 + bp;
    } else {
        lin -= 207;
        int bp = lin%25, qt = lin/25;
        khkw = KHKW5; q0 = qt*128;
        base = g_u5 + (size_t)n*U5IMG + (size_t)bp*64*KHKW5 + q0;
        sf = g_sf5 + n*25600 + bp*1024;
        pi = 160 + n*25 + bp;
    }
    int qlim = khkw - q0; if(qlim>128) qlim=128;

    if(t<64) ve[t]=g_veff[pi*64+t];
    for(int i=t;i<4096;i+=256){
        int c=i>>6, j2=i&63;
        unsigned v = 0;
        if(j2*2 < qlim) v = *(const unsigned*)&base[(size_t)c*khkw + j2*2];
        *(unsigned*)&Vs[c*130 + j2*2] = v;
    }
    __syncthreads();
    {
        int j2=t&63, cg=t>>6;
        float sx=0.f, sy=0.f;
        #pragma unroll 8
        for(int cc=cg*16; cc<cg*16+16; cc++){
            float2 f = __half22float2(*(const __half2*)&Vs[cc*130 + j2*2]);
            float w = ve[cc];
            sx += w*f.x; sy += w*f.y;
        }
        part[cg*128 + j2*2]   = sx;
        part[cg*128 + j2*2+1] = sy;
    }
    __syncthreads();
    if(t<128 && t<qlim){
        float sd = part[t]+part[128+t]+part[256+t]+part[384+t] + g_beff[pi];
        sf[q0 + t] = sigf(sd);
    }
}

// ================ K6: vsh-only multiplier + HMMA GEMM (R11, 32px tiles) ================
__global__ void __launch_bounds__(256) k6(const float* __restrict__ x, float* __restrict__ out){
    __shared__ __align__(16) __half vsh[32*264];     // [px][k], rows 192..255 = x
    __shared__ float s1s[32], icntS[32];
    __shared__ int q5s[32], cp05s[32];
    __shared__ int q3s[4][32], cp03s[4][32];
    __shared__ int nsegS[32];

    int t = threadIdx.x;
    int wt = blockIdx.x, h = blockIdx.y, n = blockIdx.z;
    int w0 = wt*32;

    const __half* exg = g_ex + (size_t)n*NO*HW + (size_t)h*Wd + w0;
    for(int i=t;i<768;i+=256){
        int k=i>>2, q=(i&3)*8;
        uint4 raw = *(const uint4*)&exg[(size_t)k*HW + q];
        const __half* hp = (const __half*)&raw;
        #pragma unroll
        for(int j=0;j<8;j++) vsh[(q+j)*264 + k] = hp[j];
    }
    const float* xp = x + (size_t)n*64*HW + (size_t)h*Wd + w0;
    for(int i=t;i<2048;i+=256){
        int c=i>>5, px=i&31;
        vsh[px*264 + 192 + c] = __float2half(xp[(size_t)c*HW+px]);
    }
    if(t<32){
        int w = w0 + t;
        int rp5 = ((h&31)*32 + (w&31))*P5 + (h>>5)*5 + (w>>5);
        q5s[t] = rp5 & 1023; cp05s[t] = rp5 >> 10;
        int R[2], C[2];
        int nr = cover3(h, R), nc = cover3(w, C);
        nsegS[t] = nr*nc;
        icntS[t] = 1.f/(float)(nr*nc);
        for(int ri=0;ri<nr;ri++)
            for(int cj=0;cj<nc;cj++){
                int ph=R[ri], pw=C[cj];
                int rp3 = ((h-53*ph)*54 + (w-53*pw))*P3 + ph*3 + pw;
                int s = ri*nc + cj;
                cp03s[s][t] = rp3 / KHKW3;
                q3s[s][t]   = rp3 % KHKW3;
            }
    }
    __syncthreads();

    if(t<32){
        float sd = g_beff[n];
        const float* ve = &g_veff[n*64];
        #pragma unroll
        for(int c=0;c<64;c++) sd += ve[c]*__half2float(vsh[t*264+c]);
        s1s[t] = sigf(sd);
    }
    __syncthreads();

    {
        int lane = t&31, wp = t>>5;
        int ci0 = lane*2;
        #pragma unroll
        for(int j=0;j<12;j++){
            int idx = wp + j*8;
            int g32 = idx>>5, pix = idx&31;
            int k = (g32<<6) + ci0;
            __half2* cell = (__half2*)&vsh[pix*264 + k];
            float2 exv = __half22float2(*cell);
            float m0, m1;
            if(g32==0){
                float s1 = s1s[pix];
                m0 = g_gt[n*64+ci0  ] + s1;
                m1 = g_gt[n*64+ci0+1] + s1;
            } else if(g32==2){
                int q5 = q5s[pix];
                int cpv0 = cp05s[pix] + 25*ci0;
                int cpv1 = cpv0 + 25;
                int bp0=cpv0>>6, cp0=cpv0&63, bp1=cpv1>>6, cp1=cpv1&63;
                m0 = g_gt[(160+n*25+bp0)*64+cp0] + g_sf5[n*25600 + (bp0<<10) + q5];
                m1 = g_gt[(160+n*25+bp1)*64+cp1] + g_sf5[n*25600 + (bp1<<10) + q5];
            } else {
                m0 = 0.f; m1 = 0.f;
                int ns = nsegS[pix];
                #pragma unroll
                for(int s=0;s<4;s++){
                    if(s>=ns) break;
                    int q3 = q3s[s][pix];
                    int cpv0 = cp03s[s][pix] + 9*ci0;
                    int cpv1 = cpv0 + 9;
                    int bp0=cpv0>>6, cp0=cpv0&63, bp1=cpv1>>6, cp1=cpv1&63;
                    m0 += g_gt[(16+n*9+bp0)*64+cp0] + g_sf3[n*A3 + bp0*KHKW3 + q3];
                    m1 += g_gt[(16+n*9+bp1)*64+cp1] + g_sf3[n*A3 + bp1*KHKW3 + q3];
                }
                float ic = icntS[pix];
                m0 *= ic; m1 *= ic;
            }
            exv.x *= (1.f + m0);
            exv.y *= (1.f + m1);
            *cell = __floats2half2_rn(exv.x, exv.y);
        }
    }
    __syncthreads();

    int lane = t&31, w = t>>5;
    int g = lane>>2, tig = lane&3;
    int mt = w&3, nt0 = (w>>2)*2, nt1 = nt0+1;
    int ob0 = mt*16;

    float vb0 = __ldg(&g_vb[ob0+g]), vb1 = __ldg(&g_vb[ob0+g+8]);
    float c00=vb0, c01=vb0, c02=vb1, c03=vb1;
    float c10=vb0, c11=vb0, c12=vb1, c13=vb1;

    const uint4* wa = g_WhA4 + mt*512 + lane;
    const __half* b0base = &vsh[(nt0*8+g)*264 + tig*2];
    const __half* b1base = &vsh[(nt1*8+g)*264 + tig*2];

    #pragma unroll
    for(int kt=0;kt<16;kt++){
        uint4 a = __ldg(&wa[kt*32]);
        int k0 = kt*16;
        unsigned p00 = *(const unsigned*)&b0base[k0];
        unsigned p01 = *(const unsigned*)&b0base[k0+8];
        MMA16816(c00,c01,c02,c03, a, p00,p01);
        unsigned p10 = *(const unsigned*)&b1base[k0];
        unsigned p11 = *(const unsigned*)&b1base[k0+8];
        MMA16816(c10,c11,c12,c13, a, p10,p11);
    }

    float* og = out + (size_t)n*64*HW + (size_t)h*Wd + w0;
    int px0 = nt0*8 + tig*2, px1 = nt1*8 + tig*2;
    *(float2*)&og[(size_t)(ob0+g  )*HW + px0] = make_float2(c00,c01);
    *(float2*)&og[(size_t)(ob0+g+8)*HW + px0] = make_float2(c02,c03);
    *(float2*)&og[(size_t)(ob0+g  )*HW + px1] = make_float2(c10,c11);
    *(float2*)&og[(size_t)(ob0+g+8)*HW + px1] = make_float2(c12,c13);
}

// ================ launch ================
extern "C" void kernel_launch(void* const* d_in, const int* in_sizes, int n_in,
                              void* d_out, int out_size){
    const float* x      = (const float*)d_in[0];
    const float* exp_w  = (const float*)d_in[1];
    const float* exp_b  = (const float*)d_in[2];
    const float* res_w  = (const float*)d_in[3];
    const float* res_b  = (const float*)d_in[4];
    const float* fus_w  = (const float*)d_in[5];
    const float* fus_b  = (const float*)d_in[6];
    const float* chwv_w = (const float*)d_in[7];
    const float* chwv_b = (const float*)d_in[8];
    const float* chwq_w = (const float*)d_in[9];
    const float* chwq_b = (const float*)d_in[10];
    const float* chwz_w = (const float*)d_in[11];
    const float* chwz_b = (const float*)d_in[12];
    const float* ln_g   = (const float*)d_in[13];
    const float* ln_b   = (const float*)d_in[14];
    const float* spwv_w = (const float*)d_in[15];
    const float* spwv_b = (const float*)d_in[16];
    const float* spwq_w = (const float*)d_in[17];
    const float* spwq_b = (const float*)d_in[18];
    float* out = (float*)d_out;

    k_zero<<<(NPI*64+255)/256, 256>>>();
    k_wprep<<<1, 256>>>(exp_w, res_w, res_b, fus_w, fus_b);

    k1<<<dim3(Wd/32, Hh, NIMG), 256>>>(x, exp_b, chwq_w, chwq_b);

    k2_5<<<dim3(32,NIMG), 256>>>();
    k2_3<<<dim3(54,NIMG), 256>>>();

    k_stats<<<dim3(407, 1, NIMG), 256>>>(chwq_w, chwq_b);

    k4<<<NPI, 64>>>(chwv_w, chwv_b, chwz_w, chwz_b, ln_g, ln_b,
                    spwq_w, spwq_b, spwv_w, spwv_b);

    k_sfield<<<dim3(407, 1, NIMG), 256>>>();

    // K6 processes ONE row per block -> full Hh grid (R13 bug: was Hh/2)
    k6<<<dim3(Wd/32, Hh, NIMG), 256>>>(x, out);
}

// round 15
// speedup vs baseline: 1.1601x; 1.0158x over previous
#include <cuda_runtime.h>
#include <cuda_fp16.h>
#include <math.h>

typedef unsigned long long u64;

#define NIMG 16
#define NO   192
#define Hh   160
#define Wd   160
#define HW   25600

#define KHKW3 2916
#define P3    9
#define A3    26244
#define U3IMG 1679616
#define KHKW5 1024
#define P5    25
#define A5    25600
#define U5IMG 1638400
#define NPI   560

// ---------------- scratch ----------------
__device__ __align__(16) __half g_ex[(size_t)NIMG*NO*HW];
__device__ __align__(16) __half g_u3[(size_t)NIMG*U3IMG];
__device__ __align__(16) __half g_u5[(size_t)NIMG*U5IMG];
__device__ __align__(16) float g_sf3[NIMG*P3*KHKW3];
__device__ __align__(16) float g_sf5[NIMG*P5*KHKW5];
__device__ float g_Z[NPI], g_S[NPI*64], g_Pm[NPI*64];
__device__ float g_gt[NPI*64], g_veff[NPI*64], g_beff[NPI];
__device__ __align__(16) float g_Wall[256*64];
__device__ __align__(16) uint4 g_WhA4[4*16*32];  // K6 HMMA A-fragments [mt][kt][lane]
__device__ __align__(16) uint4 g_WK1A4[12*4*32]; // K1 HMMA A-fragments [mt][kt][lane]
__device__ float g_vb[64];
__device__ __align__(16) float g_expWt[64*NO];

// ---------------- helpers ----------------
__device__ __forceinline__ float sigf(float x){ return 1.f/(1.f+expf(-x)); }
__device__ __forceinline__ int cover3(int h, int* r){
    int n=0;
    #pragma unroll
    for(int i=0;i<3;i++){ int lo=53*i; if(h>=lo && h<=lo+53) r[n++]=i; }
    return n;
}
__device__ __forceinline__ unsigned h2pack(float a, float b){
    __half2 h = __floats2half2_rn(a,b);
    return *(unsigned*)&h;
}

#define MMA16816(c0,c1,c2,c3,a,b0,b1) \
    asm volatile("mma.sync.aligned.m16n8k16.row.col.f32.f16.f16.f32 " \
        "{%0,%1,%2,%3},{%4,%5,%6,%7},{%8,%9},{%0,%1,%2,%3};" \
        : "+f"(c0),"+f"(c1),"+f"(c2),"+f"(c3) \
        : "r"((a).x),"r"((a).y),"r"((a).z),"r"((a).w),"r"(b0),"r"(b1))

// ================ K0a: zero accumulators ================
__global__ void k_zero(){
    int i = blockIdx.x*256 + threadIdx.x;
    if(i < NPI) g_Z[i]=0.f;
    if(i < NPI*64){ g_S[i]=0.f; g_Pm[i]=0.f; }
}

// ================ K0b: weight prep ================
__global__ void k_wprep(const float* __restrict__ exp_w, const float* __restrict__ res_w,
                        const float* __restrict__ res_b, const float* __restrict__ fus_w,
                        const float* __restrict__ fus_b){
    int t = threadIdx.x;
    for(int i=t;i<64*NO;i+=256){ int c=i/NO, o=i%NO; g_expWt[i]=exp_w[o*64+c]; }
    for(int i=t;i<NO*64;i+=256){
        int k=i/64, o=i%64; float s=0.f;
        for(int c=0;c<64;c++) s += fus_w[o*64+c]*res_w[c*NO+k];
        g_Wall[i]=s;
    }
    for(int i=t;i<64*64;i+=256){ int c=i/64, o=i%64; g_Wall[(192+c)*64+o]=fus_w[o*64+c]; }
    for(int o=t;o<64;o+=256){
        float s=fus_b[o];
        for(int c=0;c<64;c++) s += fus_w[o*64+c]*res_b[c];
        g_vb[o]=s;
    }
    __syncthreads();
    for(int i=t;i<2048;i+=256){
        int mt = i>>9, kt = (i>>5)&15, lane = i&31;
        int g = lane>>2, tig = lane&3;
        int k0 = kt*16, ob0 = mt*16;
        const float* W = g_Wall;
        unsigned r0 = h2pack(W[(k0+tig*2)*64+ob0+g],     W[(k0+tig*2+1)*64+ob0+g]);
        unsigned r1 = h2pack(W[(k0+tig*2)*64+ob0+g+8],   W[(k0+tig*2+1)*64+ob0+g+8]);
        unsigned r2 = h2pack(W[(k0+tig*2+8)*64+ob0+g],   W[(k0+tig*2+9)*64+ob0+g]);
        unsigned r3 = h2pack(W[(k0+tig*2+8)*64+ob0+g+8], W[(k0+tig*2+9)*64+ob0+g+8]);
        g_WhA4[i] = make_uint4(r0,r1,r2,r3);
    }
    for(int i=t;i<1536;i+=256){
        int mt = i>>7, kt = (i>>5)&3, lane = i&31;
        int g = lane>>2, tig = lane&3;
        int k0 = kt*16, ob0 = mt*16;
        const float* W = g_expWt;
        unsigned r0 = h2pack(W[(k0+tig*2)*NO+ob0+g],     W[(k0+tig*2+1)*NO+ob0+g]);
        unsigned r1 = h2pack(W[(k0+tig*2)*NO+ob0+g+8],   W[(k0+tig*2+1)*NO+ob0+g+8]);
        unsigned r2 = h2pack(W[(k0+tig*2+8)*NO+ob0+g],   W[(k0+tig*2+9)*NO+ob0+g]);
        unsigned r3 = h2pack(W[(k0+tig*2+8)*NO+ob0+g+8], W[(k0+tig*2+9)*NO+ob0+g+8]);
        g_WK1A4[i] = make_uint4(r0,r1,r2,r3);
    }
}

// ================ K1: HMMA ex = Wexp @ x + fused win1 stats ================
__global__ void __launch_bounds__(256) k1(const float* __restrict__ x,
                                          const float* __restrict__ exp_b,
                                          const float* __restrict__ wq,
                                          const float* __restrict__ wqb){
    __shared__ __align__(16) __half xh[32*72];
    __shared__ __align__(16) __half exsh[192*40];
    __shared__ float es[32];
    int t = threadIdx.x;
    int wt = blockIdx.x, h = blockIdx.y, n = blockIdx.z;
    int w0 = wt*32;

    const float* xp = x + (size_t)n*64*HW + (size_t)h*Wd + w0;
    for(int i=t;i<512;i+=256){
        int c=i>>3, p4=(i&7)*4;
        float4 v = *(const float4*)&xp[(size_t)c*HW + p4];
        xh[(p4  )*72 + c] = __float2half(v.x);
        xh[(p4+1)*72 + c] = __float2half(v.y);
        xh[(p4+2)*72 + c] = __float2half(v.z);
        xh[(p4+3)*72 + c] = __float2half(v.w);
    }
    __syncthreads();

    int lane = t&31, w = t>>5;
    int g = lane>>2, tig = lane&3;
    int mtb = (w&3)*3, nt0 = (w>>2)*2, nt1 = nt0+1;
    int px0 = nt0*8 + tig*2, px1 = nt1*8 + tig*2;

    const __half* b0base = &xh[(nt0*8+g)*72 + tig*2];
    const __half* b1base = &xh[(nt1*8+g)*72 + tig*2];
    unsigned bf0[8], bf1[8];
    #pragma unroll
    for(int kt=0;kt<4;kt++){
        bf0[kt*2  ] = *(const unsigned*)&b0base[kt*16];
        bf0[kt*2+1] = *(const unsigned*)&b0base[kt*16+8];
        bf1[kt*2  ] = *(const unsigned*)&b1base[kt*16];
        bf1[kt*2+1] = *(const unsigned*)&b1base[kt*16+8];
    }

    #pragma unroll
    for(int mi=0;mi<3;mi++){
        int mt = mtb+mi, ob0 = mt*16;
        float c00=0,c01=0,c02=0,c03=0, c10=0,c11=0,c12=0,c13=0;
        const uint4* wa = g_WK1A4 + mt*128 + lane;
        #pragma unroll
        for(int kt=0;kt<4;kt++){
            uint4 a = __ldg(&wa[kt*32]);
            MMA16816(c00,c01,c02,c03, a, bf0[kt*2],bf0[kt*2+1]);
            MMA16816(c10,c11,c12,c13, a, bf1[kt*2],bf1[kt*2+1]);
        }
        float b0 = __ldg(&exp_b[ob0+g]), b1 = __ldg(&exp_b[ob0+g+8]);
        *(unsigned*)&exsh[(ob0+g  )*40 + px0] = h2pack(c00+b0, c01+b0);
        *(unsigned*)&exsh[(ob0+g+8)*40 + px0] = h2pack(c02+b1, c03+b1);
        *(unsigned*)&exsh[(ob0+g  )*40 + px1] = h2pack(c10+b0, c11+b0);
        *(unsigned*)&exsh[(ob0+g+8)*40 + px1] = h2pack(c12+b1, c13+b1);
    }
    __syncthreads();

    __half* exg = g_ex + (size_t)n*NO*HW + (size_t)h*Wd + w0;
    for(int i=t;i<768;i+=256){
        int r=i>>2, q=(i&3)*8;
        *(uint4*)&exg[(size_t)r*HW + q] = *(const uint4*)&exsh[r*40 + q];
    }

    if(t<32){
        float qd = wqb[0];
        #pragma unroll
        for(int c=0;c<64;c++) qd += wq[c]*__half2float(exsh[c*40+t]);
        float e = expf(qd);
        es[t]=e;
        float z=e;
        for(int off=16;off;off>>=1) z += __shfl_xor_sync(0xffffffffu,z,off);
        if(t==0) atomicAdd(&g_Z[n], z);
    }
    __syncthreads();
    if(t<64){
        float Ps=0.f, Ss=0.f;
        #pragma unroll
        for(int px=0;px<32;px++){ float v=__half2float(exsh[t*40+px]); Ps+=v; Ss+=v*es[px]; }
        atomicAdd(&g_S[n*64+t], Ss);
        atomicAdd(&g_Pm[n*64+t], Ps);
    }
}

// ================ K2: fused repack (win5: blocks 0..31, win3: blocks 32..85) ================
__global__ void __launch_bounds__(256) k2(){
    __shared__ __align__(16) __half rb[8][800];
    int n = blockIdx.y;
    int wp = threadIdx.x >> 5, lane = threadIdx.x & 31;
    if(blockIdx.x < 32){
        int y = blockIdx.x;
        for(int cit=0; cit<8; cit++){
            int ci = cit*8 + wp;
            const __half* src = g_ex + (size_t)n*NO*HW + (size_t)(128+ci)*HW;
            #pragma unroll
            for(int ph=0; ph<5; ph++){
                const __half2* row2 = (const __half2*)(src + (size_t)(ph*32+y)*Wd);
                #pragma unroll
                for(int it=0; it<3; it++){
                    int idx = lane + it*32;
                    if(idx<80){
                        __half2 v = row2[idx];
                        int w = idx*2, pw = w>>5, xx = w&31;
                        rb[wp][xx*25 + ph*5 + pw]     = __low2half(v);
                        rb[wp][(xx+1)*25 + ph*5 + pw] = __high2half(v);
                    }
                }
            }
            __syncwarp();
            uint4* dst = (uint4*)(g_u5 + (size_t)n*U5IMG + (size_t)(ci*1024 + y*32)*25);
            const uint4* s = (const uint4*)rb[wp];
            #pragma unroll
            for(int it=0; it<4; it++){
                int k = lane + it*32;
                if(k < 100) dst[k] = s[k];
            }
            __syncwarp();
        }
    } else {
        int yy = blockIdx.x - 32;
        for(int cit=0; cit<8; cit++){
            int ci = cit*8 + wp;
            const __half* src = g_ex + (size_t)n*NO*HW + (size_t)(64+ci)*HW;
            #pragma unroll
            for(int ph=0; ph<3; ph++){
                const __half2* row2 = (const __half2*)(src + (size_t)(53*ph+yy)*Wd);
                #pragma unroll
                for(int it=0; it<3; it++){
                    int idx = lane + it*32;
                    if(idx<80){
                        __half2 v = row2[idx];
                        int w0_ = idx*2;
                        __half hv[2] = {__low2half(v), __high2half(v)};
                        #pragma unroll
                        for(int hh=0; hh<2; hh++){
                            int w = w0_ + hh;
                            #pragma unroll
                            for(int pw=0; pw<3; pw++){
                                int xx = w - 53*pw;
                                if(xx>=0 && xx<54) rb[wp][xx*9 + ph*3 + pw] = hv[hh];
                            }
                        }
                    }
                }
            }
            __syncwarp();
            unsigned* dst = (unsigned*)(g_u3 + (size_t)n*U3IMG + (size_t)ci*A3 + (size_t)yy*486);
            const unsigned* s = (const unsigned*)rb[wp];
            #pragma unroll
            for(int it=0; it<8; it++){
                int k = lane + it*32;
                if(k < 243) dst[k] = s[k];
            }
            __syncwarp();
        }
    }
}

// ================ K3: fused stats (win3 + win5 in one launch) ================
__global__ void __launch_bounds__(256) k_stats(const float* __restrict__ wq,
                                               const float* __restrict__ wqb){
    __shared__ __half Vs[64*130];
    __shared__ float part[4*128];
    __shared__ float es[128];
    int lin = blockIdx.x, n = blockIdx.z;
    int t = threadIdx.x;
    const __half* base; int khkw, pi, q0;
    if(lin < 207){
        int bp = lin%9, qt = lin/9;
        khkw = KHKW3; q0 = qt*128;
        base = g_u3 + (size_t)n*U3IMG + (size_t)bp*64*KHKW3 + q0;
        pi = 16 + n*9 + bp;
    } else {
        lin -= 207;
        int bp = lin%25, qt = lin/25;
        khkw = KHKW5; q0 = qt*128;
        base = g_u5 + (size_t)n*U5IMG + (size_t)bp*64*KHKW5 + q0;
        pi = 160 + n*25 + bp;
    }
    int qlim = khkw - q0; if(qlim>128) qlim=128;

    for(int i=t;i<4096;i+=256){
        int c=i>>6, j2=i&63;
        unsigned v = 0;
        if(j2*2 < qlim) v = *(const unsigned*)&base[(size_t)c*khkw + j2*2];
        *(unsigned*)&Vs[c*130 + j2*2] = v;
    }
    __syncthreads();
    {
        int j2=t&63, cg=t>>6;
        float sx=0.f, sy=0.f;
        #pragma unroll 8
        for(int cc=cg*16; cc<cg*16+16; cc++){
            float2 f = __half22float2(*(const __half2*)&Vs[cc*130 + j2*2]);
            float w = wq[cc];
            sx += w*f.x; sy += w*f.y;
        }
        part[cg*128 + j2*2]   = sx;
        part[cg*128 + j2*2+1] = sy;
    }
    __syncthreads();
    if(t<128){
        float qd = part[t]+part[128+t]+part[256+t]+part[384+t] + wqb[0];
        float e = (t<qlim) ? expf(qd) : 0.f;
        es[t]=e;
        float z=e;
        for(int off=16;off;off>>=1) z += __shfl_xor_sync(0xffffffffu,z,off);
        if((t&31)==0) atomicAdd(&g_Z[pi], z);
    }
    __syncthreads();
    {
        int c=t&63, jg=t>>6;
        float ss=0.f, pm=0.f;
        #pragma unroll 8
        for(int j2=jg*16; j2<jg*16+16; j2++){
            float2 f = __half22float2(*(const __half2*)&Vs[c*130 + j2*2]);
            ss += f.x*es[2*j2] + f.y*es[2*j2+1];
            pm += f.x + f.y;
        }
        atomicAdd(&g_S[pi*64+c], ss);
        atomicAdd(&g_Pm[pi*64+c], pm);
    }
}

// ================ K4: per-pseudo-image finalize ================
__global__ void __launch_bounds__(64) k4(const float* __restrict__ chwv_w, const float* __restrict__ chwv_b,
                                         const float* __restrict__ chwz_w, const float* __restrict__ chwz_b,
                                         const float* __restrict__ ln_g,  const float* __restrict__ ln_b,
                                         const float* __restrict__ spwq_w,const float* __restrict__ spwq_b,
                                         const float* __restrict__ spwv_w,const float* __restrict__ spwv_b){
    int p = blockIdx.x, t = threadIdx.x;
    float hw = (p<16) ? 25600.f : ((p<160) ? 2916.f : 1024.f);
    __shared__ float xbar[64], pmean[64], wz[32], red[64], swq[32];

    float Zinv = 1.f/g_Z[p];
    xbar[t]  = g_S[p*64+t]*Zinv;
    pmean[t] = g_Pm[p*64+t]/hw;
    __syncthreads();

    if(t<32){
        float s = chwv_b[t];
        for(int c=0;c<64;c++) s += chwv_w[t*64+c]*xbar[c];
        wz[t]=s;
    }
    __syncthreads();

    float z = chwz_b[t];
    for(int j=0;j<32;j++) z += chwz_w[t*32+j]*wz[j];

    red[t]=z; __syncthreads();
    for(int s=32;s>0;s>>=1){ if(t<s) red[t]+=red[t+s]; __syncthreads(); }
    float mu = red[0]*(1.f/64.f); __syncthreads();
    float d = z-mu;
    red[t]=d*d; __syncthreads();
    for(int s=32;s>0;s>>=1){ if(t<s) red[t]+=red[t+s]; __syncthreads(); }
    float var = red[0]*(1.f/64.f);

    float zn = d*rsqrtf(var+1e-5f)*ln_g[t] + ln_b[t];
    g_gt[p*64+t] = sigf(zn);
    __syncthreads();

    if(t<32){
        float s = spwq_b[t];
        for(int c=0;c<64;c++) s += spwq_w[t*64+c]*pmean[c];
        float m=s;
        for(int off=16;off;off>>=1) m=fmaxf(m,__shfl_xor_sync(0xffffffffu,m,off));
        float e=expf(s-m), sum=e;
        for(int off=16;off;off>>=1) sum+=__shfl_xor_sync(0xffffffffu,sum,off);
        swq[t]=e/sum;
    }
    __syncthreads();

    float v=0.f;
    for(int j=0;j<32;j++) v += swq[j]*spwv_w[j*64+t];
    g_veff[p*64+t]=v;
    if(t==0){
        float b=0.f;
        for(int j=0;j<32;j++) b += swq[j]*spwv_b[j];
        g_beff[p]=b;
    }
}

// ================ K5: fused s-field (win3 + win5 in one launch) ================
__global__ void __launch_bounds__(256) k_sfield(){
    __shared__ __half Vs[64*130];
    __shared__ float part[4*128];
    __shared__ float ve[64];
    int lin = blockIdx.x, n = blockIdx.z;
    int t = threadIdx.x;
    const __half* base; float* sf; int khkw, pi, q0;
    if(lin < 207){
        int bp = lin%9, qt = lin/9;
        khkw = KHKW3; q0 = qt*128;
        base = g_u3 + (size_t)n*U3IMG + (size_t)bp*64*KHKW3 + q0;
        sf = g_sf3 + n*A3 + bp*KHKW3;
        pi = 16 + n*9 + bp;
    } else {
        lin -= 207;
        int bp = lin%25, qt = lin/25;
        khkw = KHKW5; q0 = qt*128;
        base = g_u5 + (size_t)n*U5IMG + (size_t)bp*64*KHKW5 + q0;
        sf = g_sf5 + n*25600 + bp*1024;
        pi = 160 + n*25 + bp;
    }
    int qlim = khkw - q0; if(qlim>128) qlim=128;

    if(t<64) ve[t]=g_veff[pi*64+t];
    for(int i=t;i<4096;i+=256){
        int c=i>>6, j2=i&63;
        unsigned v = 0;
        if(j2*2 < qlim) v = *(const unsigned*)&base[(size_t)c*khkw + j2*2];
        *(unsigned*)&Vs[c*130 + j2*2] = v;
    }
    __syncthreads();
    {
        int j2=t&63, cg=t>>6;
        float sx=0.f, sy=0.f;
        #pragma unroll 8
        for(int cc=cg*16; cc<cg*16+16; cc++){
            float2 f = __half22float2(*(const __half2*)&Vs[cc*130 + j2*2]);
            float w = ve[cc];
            sx += w*f.x; sy += w*f.y;
        }
        part[cg*128 + j2*2]   = sx;
        part[cg*128 + j2*2+1] = sy;
    }
    __syncthreads();
    if(t<128 && t<qlim){
        float sd = part[t]+part[128+t]+part[256+t]+part[384+t] + g_beff[pi];
        sf[q0 + t] = sigf(sd);
    }
}

// ================ K6: swizzled vsh multiplier + HMMA GEMM ================
// logical vsh(px,k) stored at vsh[px*264 + (k ^ (px&24))]
__global__ void __launch_bounds__(256) k6(const float* __restrict__ x, float* __restrict__ out){
    __shared__ __align__(16) __half vsh[32*264];
    __shared__ float s1s[32], icntS[32];
    __shared__ int q5s[32], cp05s[32];
    __shared__ int q3s[4][32], cp03s[4][32];
    __shared__ int nsegS[32];

    int t = threadIdx.x;
    int wt = blockIdx.x, h = blockIdx.y, n = blockIdx.z;
    int w0 = wt*32;

    // ex tile -> vsh (swizzled scatter; (q+j)&24 == q since q mult of 8, j<8)
    const __half* exg = g_ex + (size_t)n*NO*HW + (size_t)h*Wd + w0;
    for(int i=t;i<768;i+=256){
        int k=i>>2, q=(i&3)*8;
        uint4 raw = *(const uint4*)&exg[(size_t)k*HW + q];
        const __half* hp = (const __half*)&raw;
        int ks = k ^ q;
        #pragma unroll
        for(int j=0;j<8;j++) vsh[(q+j)*264 + ks] = hp[j];
    }
    // x -> vsh rows 192..255 (swizzled)
    const float* xp = x + (size_t)n*64*HW + (size_t)h*Wd + w0;
    for(int i=t;i<2048;i+=256){
        int c=i>>5, px=i&31;
        vsh[px*264 + ((192+c) ^ (px&24))] = __float2half(xp[(size_t)c*HW+px]);
    }
    if(t<32){
        int w = w0 + t;
        int rp5 = ((h&31)*32 + (w&31))*P5 + (h>>5)*5 + (w>>5);
        q5s[t] = rp5 & 1023; cp05s[t] = rp5 >> 10;
        int R[2], C[2];
        int nr = cover3(h, R), nc = cover3(w, C);
        nsegS[t] = nr*nc;
        icntS[t] = 1.f/(float)(nr*nc);
        for(int ri=0;ri<nr;ri++)
            for(int cj=0;cj<nc;cj++){
                int ph=R[ri], pw=C[cj];
                int rp3 = ((h-53*ph)*54 + (w-53*pw))*P3 + ph*3 + pw;
                int s = ri*nc + cj;
                cp03s[s][t] = rp3 / KHKW3;
                q3s[s][t]   = rp3 % KHKW3;
            }
    }
    __syncthreads();

    // win1 s-field (swizzled reads)
    if(t<32){
        float sd = g_beff[n];
        const float* ve = &g_veff[n*64];
        int C = t&24;
        #pragma unroll
        for(int c=0;c<64;c++) sd += ve[c]*__half2float(vsh[t*264 + (c^C)]);
        s1s[t] = sigf(sd);
    }
    __syncthreads();

    // multiplier: conflict-free half2 RMW (swizzled)
    {
        int lane = t&31, wp = t>>5;
        int ci0 = lane*2;
        #pragma unroll
        for(int j=0;j<12;j++){
            int idx = wp + j*8;
            int g32 = idx>>5, pix = idx&31;
            int k = (g32<<6) + ci0;
            __half2* cell = (__half2*)&vsh[pix*264 + (k ^ (pix&24))];
            float2 exv = __half22float2(*cell);
            float m0, m1;
            if(g32==0){
                float s1 = s1s[pix];
                m0 = g_gt[n*64+ci0  ] + s1;
                m1 = g_gt[n*64+ci0+1] + s1;
            } else if(g32==2){
                int q5 = q5s[pix];
                int cpv0 = cp05s[pix] + 25*ci0;
                int cpv1 = cpv0 + 25;
                int bp0=cpv0>>6, cp0=cpv0&63, bp1=cpv1>>6, cp1=cpv1&63;
                m0 = g_gt[(160+n*25+bp0)*64+cp0] + g_sf5[n*25600 + (bp0<<10) + q5];
                m1 = g_gt[(160+n*25+bp1)*64+cp1] + g_sf5[n*25600 + (bp1<<10) + q5];
            } else {
                m0 = 0.f; m1 = 0.f;
                int ns = nsegS[pix];
                #pragma unroll
                for(int s=0;s<4;s++){
                    if(s>=ns) break;
                    int q3 = q3s[s][pix];
                    int cpv0 = cp03s[s][pix] + 9*ci0;
                    int cpv1 = cpv0 + 9;
                    int bp0=cpv0>>6, cp0=cpv0&63, bp1=cpv1>>6, cp1=cpv1&63;
                    m0 += g_gt[(16+n*9+bp0)*64+cp0] + g_sf3[n*A3 + bp0*KHKW3 + q3];
                    m1 += g_gt[(16+n*9+bp1)*64+cp1] + g_sf3[n*A3 + bp1*KHKW3 + q3];
                }
                float ic = icntS[pix];
                m0 *= ic; m1 *= ic;
            }
            exv.x *= (1.f + m0);
            exv.y *= (1.f + m1);
            *cell = __floats2half2_rn(exv.x, exv.y);
        }
    }
    __syncthreads();

    // HMMA GEMM (swizzled B-fragment loads; C const per fragment row)
    int lane = t&31, w = t>>5;
    int g = lane>>2, tig = lane&3;
    int mt = w&3, nt0 = (w>>2)*2, nt1 = nt0+1;
    int ob0 = mt*16;

    float vb0 = __ldg(&g_vb[ob0+g]), vb1 = __ldg(&g_vb[ob0+g+8]);
    float c00=vb0, c01=vb0, c02=vb1, c03=vb1;
    float c10=vb0, c11=vb0, c12=vb1, c13=vb1;

    const uint4* wa = g_WhA4 + mt*512 + lane;
    int row0 = nt0*8+g, row1 = nt1*8+g;
    int C0 = row0&24, C1 = row1&24;
    const __half* b0r = &vsh[row0*264];
    const __half* b1r = &vsh[row1*264];

    #pragma unroll
    for(int kt=0;kt<16;kt++){
        uint4 a = __ldg(&wa[kt*32]);
        int x0 = (kt*16 + tig*2) ^ C0;     // bit3 of (kt*16+tig*2) is 0 -> +8 == ^8
        int x1 = (kt*16 + tig*2) ^ C1;
        unsigned p00 = *(const unsigned*)&b0r[x0];
        unsigned p01 = *(const unsigned*)&b0r[x0^8];
        MMA16816(c00,c01,c02,c03, a, p00,p01);
        unsigned p10 = *(const unsigned*)&b1r[x1];
        unsigned p11 = *(const unsigned*)&b1r[x1^8];
        MMA16816(c10,c11,c12,c13, a, p10,p11);
    }

    float* og = out + (size_t)n*64*HW + (size_t)h*Wd + w0;
    int px0 = nt0*8 + tig*2, px1 = nt1*8 + tig*2;
    *(float2*)&og[(size_t)(ob0+g  )*HW + px0] = make_float2(c00,c01);
    *(float2*)&og[(size_t)(ob0+g+8)*HW + px0] = make_float2(c02,c03);
    *(float2*)&og[(size_t)(ob0+g  )*HW + px1] = make_float2(c10,c11);
    *(float2*)&og[(size_t)(ob0+g+8)*HW + px1] = make_float2(c12,c13);
}

// ================ launch ================
extern "C" void kernel_launch(void* const* d_in, const int* in_sizes, int n_in,
                              void* d_out, int out_size){
    const float* x      = (const float*)d_in[0];
    const float* exp_w  = (const float*)d_in[1];
    const float* exp_b  = (const float*)d_in[2];
    const float* res_w  = (const float*)d_in[3];
    const float* res_b  = (const float*)d_in[4];
    const float* fus_w  = (const float*)d_in[5];
    const float* fus_b  = (const float*)d_in[6];
    const float* chwv_w = (const float*)d_in[7];
    const float* chwv_b = (const float*)d_in[8];
    const float* chwq_w = (const float*)d_in[9];
    const float* chwq_b = (const float*)d_in[10];
    const float* chwz_w = (const float*)d_in[11];
    const float* chwz_b = (const float*)d_in[12];
    const float* ln_g   = (const float*)d_in[13];
    const float* ln_b   = (const float*)d_in[14];
    const float* spwv_w = (const float*)d_in[15];
    const float* spwv_b = (const float*)d_in[16];
    const float* spwq_w = (const float*)d_in[17];
    const float* spwq_b = (const float*)d_in[18];
    float* out = (float*)d_out;

    k_zero<<<(NPI*64+255)/256, 256>>>();
    k_wprep<<<1, 256>>>(exp_w, res_w, res_b, fus_w, fus_b);

    k1<<<dim3(Wd/32, Hh, NIMG), 256>>>(x, exp_b, chwq_w, chwq_b);

    k2<<<dim3(86, NIMG), 256>>>();

    k_stats<<<dim3(407, 1, NIMG), 256>>>(chwq_w, chwq_b);

    k4<<<NPI, 64>>>(chwv_w, chwv_b, chwz_w, chwz_b, ln_g, ln_b,
                    spwq_w, spwq_b, spwv_w, spwv_b);

    k_sfield<<<dim3(407, 1, NIMG), 256>>>();

    k6<<<dim3(Wd/32, Hh, NIMG), 256>>>(x, out);
}

// round 16
// speedup vs baseline: 1.2527x; 1.0798x over previous
#include <cuda_runtime.h>
#include <cuda_fp16.h>
#include <math.h>

typedef unsigned long long u64;

#define NIMG 16
#define NO   192
#define Hh   160
#define Wd   160
#define HW   25600

#define KHKW3 2916
#define P3    9
#define A3    26244
#define U3IMG 1679616
#define KHKW5 1024
#define P5    25
#define A5    25600
#define U5IMG 1638400
#define NPI   560

// ---------------- scratch ----------------
__device__ __align__(16) __half g_ex[(size_t)NIMG*NO*HW];
__device__ __align__(16) __half g_u3[(size_t)NIMG*U3IMG];
__device__ __align__(16) __half g_u5[(size_t)NIMG*U5IMG];
__device__ __align__(16) float g_sf3[NIMG*P3*KHKW3];
__device__ __align__(16) float g_sf5[NIMG*P5*KHKW5];
__device__ float g_Z[NPI], g_S[NPI*64], g_Pm[NPI*64];
__device__ float g_gt[NPI*64], g_veff[NPI*64], g_beff[NPI];
__device__ __align__(16) float g_Wall[256*64];
__device__ __align__(16) uint4 g_WhA4[4*16*32];
__device__ __align__(16) uint4 g_WK1A4[12*4*32];
__device__ float g_vb[64];
__device__ __align__(16) float g_expWt[64*NO];

// ---------------- helpers ----------------
__device__ __forceinline__ float sigf(float x){ return 1.f/(1.f+expf(-x)); }
__device__ __forceinline__ int cover3(int h, int* r){
    int n=0;
    #pragma unroll
    for(int i=0;i<3;i++){ int lo=53*i; if(h>=lo && h<=lo+53) r[n++]=i; }
    return n;
}
__device__ __forceinline__ unsigned h2pack(float a, float b){
    __half2 h = __floats2half2_rn(a,b);
    return *(unsigned*)&h;
}

#define MMA16816(c0,c1,c2,c3,a,b0,b1) \
    asm volatile("mma.sync.aligned.m16n8k16.row.col.f32.f16.f16.f32 " \
        "{%0,%1,%2,%3},{%4,%5,%6,%7},{%8,%9},{%0,%1,%2,%3};" \
        : "+f"(c0),"+f"(c1),"+f"(c2),"+f"(c3) \
        : "r"((a).x),"r"((a).y),"r"((a).z),"r"((a).w),"r"(b0),"r"(b1))

// ================ K0a: zero accumulators ================
__global__ void k_zero(){
    int i = blockIdx.x*256 + threadIdx.x;
    if(i < NPI) g_Z[i]=0.f;
    if(i < NPI*64){ g_S[i]=0.f; g_Pm[i]=0.f; }
}

// ================ K0b: weight prep ================
__global__ void k_wprep(const float* __restrict__ exp_w, const float* __restrict__ res_w,
                        const float* __restrict__ res_b, const float* __restrict__ fus_w,
                        const float* __restrict__ fus_b){
    int t = threadIdx.x;
    for(int i=t;i<64*NO;i+=256){ int c=i/NO, o=i%NO; g_expWt[i]=exp_w[o*64+c]; }
    for(int i=t;i<NO*64;i+=256){
        int k=i/64, o=i%64; float s=0.f;
        for(int c=0;c<64;c++) s += fus_w[o*64+c]*res_w[c*NO+k];
        g_Wall[i]=s;
    }
    for(int i=t;i<64*64;i+=256){ int c=i/64, o=i%64; g_Wall[(192+c)*64+o]=fus_w[o*64+c]; }
    for(int o=t;o<64;o+=256){
        float s=fus_b[o];
        for(int c=0;c<64;c++) s += fus_w[o*64+c]*res_b[c];
        g_vb[o]=s;
    }
    __syncthreads();
    for(int i=t;i<2048;i+=256){
        int mt = i>>9, kt = (i>>5)&15, lane = i&31;
        int g = lane>>2, tig = lane&3;
        int k0 = kt*16, ob0 = mt*16;
        const float* W = g_Wall;
        unsigned r0 = h2pack(W[(k0+tig*2)*64+ob0+g],     W[(k0+tig*2+1)*64+ob0+g]);
        unsigned r1 = h2pack(W[(k0+tig*2)*64+ob0+g+8],   W[(k0+tig*2+1)*64+ob0+g+8]);
        unsigned r2 = h2pack(W[(k0+tig*2+8)*64+ob0+g],   W[(k0+tig*2+9)*64+ob0+g]);
        unsigned r3 = h2pack(W[(k0+tig*2+8)*64+ob0+g+8], W[(k0+tig*2+9)*64+ob0+g+8]);
        g_WhA4[i] = make_uint4(r0,r1,r2,r3);
    }
    for(int i=t;i<1536;i+=256){
        int mt = i>>7, kt = (i>>5)&3, lane = i&31;
        int g = lane>>2, tig = lane&3;
        int k0 = kt*16, ob0 = mt*16;
        const float* W = g_expWt;
        unsigned r0 = h2pack(W[(k0+tig*2)*NO+ob0+g],     W[(k0+tig*2+1)*NO+ob0+g]);
        unsigned r1 = h2pack(W[(k0+tig*2)*NO+ob0+g+8],   W[(k0+tig*2+1)*NO+ob0+g+8]);
        unsigned r2 = h2pack(W[(k0+tig*2+8)*NO+ob0+g],   W[(k0+tig*2+9)*NO+ob0+g]);
        unsigned r3 = h2pack(W[(k0+tig*2+8)*NO+ob0+g+8], W[(k0+tig*2+9)*NO+ob0+g+8]);
        g_WK1A4[i] = make_uint4(r0,r1,r2,r3);
    }
}

// ================ K1: HMMA ex = Wexp @ x + fused win1 stats ================
__global__ void __launch_bounds__(256) k1(const float* __restrict__ x,
                                          const float* __restrict__ exp_b,
                                          const float* __restrict__ wq,
                                          const float* __restrict__ wqb){
    __shared__ __align__(16) __half xh[32*72];
    __shared__ __align__(16) __half exsh[192*40];
    __shared__ float es[32];
    int t = threadIdx.x;
    int wt = blockIdx.x, h = blockIdx.y, n = blockIdx.z;
    int w0 = wt*32;

    const float* xp = x + (size_t)n*64*HW + (size_t)h*Wd + w0;
    for(int i=t;i<512;i+=256){
        int c=i>>3, p4=(i&7)*4;
        float4 v = *(const float4*)&xp[(size_t)c*HW + p4];
        xh[(p4  )*72 + c] = __float2half(v.x);
        xh[(p4+1)*72 + c] = __float2half(v.y);
        xh[(p4+2)*72 + c] = __float2half(v.z);
        xh[(p4+3)*72 + c] = __float2half(v.w);
    }
    __syncthreads();

    int lane = t&31, w = t>>5;
    int g = lane>>2, tig = lane&3;
    int mtb = (w&3)*3, nt0 = (w>>2)*2, nt1 = nt0+1;
    int px0 = nt0*8 + tig*2, px1 = nt1*8 + tig*2;

    const __half* b0base = &xh[(nt0*8+g)*72 + tig*2];
    const __half* b1base = &xh[(nt1*8+g)*72 + tig*2];
    unsigned bf0[8], bf1[8];
    #pragma unroll
    for(int kt=0;kt<4;kt++){
        bf0[kt*2  ] = *(const unsigned*)&b0base[kt*16];
        bf0[kt*2+1] = *(const unsigned*)&b0base[kt*16+8];
        bf1[kt*2  ] = *(const unsigned*)&b1base[kt*16];
        bf1[kt*2+1] = *(const unsigned*)&b1base[kt*16+8];
    }

    #pragma unroll
    for(int mi=0;mi<3;mi++){
        int mt = mtb+mi, ob0 = mt*16;
        float c00=0,c01=0,c02=0,c03=0, c10=0,c11=0,c12=0,c13=0;
        const uint4* wa = g_WK1A4 + mt*128 + lane;
        #pragma unroll
        for(int kt=0;kt<4;kt++){
            uint4 a = __ldg(&wa[kt*32]);
            MMA16816(c00,c01,c02,c03, a, bf0[kt*2],bf0[kt*2+1]);
            MMA16816(c10,c11,c12,c13, a, bf1[kt*2],bf1[kt*2+1]);
        }
        float b0 = __ldg(&exp_b[ob0+g]), b1 = __ldg(&exp_b[ob0+g+8]);
        *(unsigned*)&exsh[(ob0+g  )*40 + px0] = h2pack(c00+b0, c01+b0);
        *(unsigned*)&exsh[(ob0+g+8)*40 + px0] = h2pack(c02+b1, c03+b1);
        *(unsigned*)&exsh[(ob0+g  )*40 + px1] = h2pack(c10+b0, c11+b0);
        *(unsigned*)&exsh[(ob0+g+8)*40 + px1] = h2pack(c12+b1, c13+b1);
    }
    __syncthreads();

    __half* exg = g_ex + (size_t)n*NO*HW + (size_t)h*Wd + w0;
    for(int i=t;i<768;i+=256){
        int r=i>>2, q=(i&3)*8;
        *(uint4*)&exg[(size_t)r*HW + q] = *(const uint4*)&exsh[r*40 + q];
    }

    if(t<32){
        float qd = wqb[0];
        #pragma unroll
        for(int c=0;c<64;c++) qd += wq[c]*__half2float(exsh[c*40+t]);
        float e = expf(qd);
        es[t]=e;
        float z=e;
        for(int off=16;off;off>>=1) z += __shfl_xor_sync(0xffffffffu,z,off);
        if(t==0) atomicAdd(&g_Z[n], z);
    }
    __syncthreads();
    if(t<64){
        float Ps=0.f, Ss=0.f;
        #pragma unroll
        for(int px=0;px<32;px++){ float v=__half2float(exsh[t*40+px]); Ps+=v; Ss+=v*es[px]; }
        atomicAdd(&g_S[n*64+t], Ss);
        atomicAdd(&g_Pm[n*64+t], Ps);
    }
}

// ================ K2: fused repack + Pm accumulation ================
__global__ void __launch_bounds__(256) k2(){
    __shared__ __align__(16) __half rb[8][800];
    int n = blockIdx.y;
    int wp = threadIdx.x >> 5, lane = threadIdx.x & 31;
    if(blockIdx.x < 32){
        int y = blockIdx.x;
        for(int cit=0; cit<8; cit++){
            int ci = cit*8 + wp;
            const __half* src = g_ex + (size_t)n*NO*HW + (size_t)(128+ci)*HW;
            #pragma unroll
            for(int ph=0; ph<5; ph++){
                const __half2* row2 = (const __half2*)(src + (size_t)(ph*32+y)*Wd);
                #pragma unroll
                for(int it=0; it<3; it++){
                    int idx = lane + it*32;
                    if(idx<80){
                        __half2 v = row2[idx];
                        int w = idx*2, pw = w>>5, xx = w&31;
                        rb[wp][xx*25 + ph*5 + pw]     = __low2half(v);
                        rb[wp][(xx+1)*25 + ph*5 + pw] = __high2half(v);
                    }
                }
            }
            __syncwarp();
            uint4* dst = (uint4*)(g_u5 + (size_t)n*U5IMG + (size_t)(ci*1024 + y*32)*25);
            const uint4* s = (const uint4*)rb[wp];
            #pragma unroll
            for(int it=0; it<4; it++){
                int k = lane + it*32;
                if(k < 100) dst[k] = s[k];
            }
            // Pm partials for win5 (run may cross one 1024 bin boundary)
            {
                int o0 = ci*25600 + y*800;
                int sb = ((o0 >> 10) + 1 << 10) - o0; if(sb > 800) sb = 800;
                float s1=0.f, s2=0.f;
                for(int i=lane;i<800;i+=32){
                    float v = __half2float(rb[wp][i]);
                    if(i<sb) s1+=v; else s2+=v;
                }
                for(int off=16;off;off>>=1){
                    s1 += __shfl_xor_sync(0xffffffffu,s1,off);
                    s2 += __shfl_xor_sync(0xffffffffu,s2,off);
                }
                if(lane==0){
                    int bin = o0>>10;
                    atomicAdd(&g_Pm[(160 + n*25 + (bin>>6))*64 + (bin&63)], s1);
                    if(sb<800){
                        int b2 = bin+1;
                        atomicAdd(&g_Pm[(160 + n*25 + (b2>>6))*64 + (b2&63)], s2);
                    }
                }
            }
            __syncwarp();
        }
    } else {
        int yy = blockIdx.x - 32;
        for(int cit=0; cit<8; cit++){
            int ci = cit*8 + wp;
            const __half* src = g_ex + (size_t)n*NO*HW + (size_t)(64+ci)*HW;
            #pragma unroll
            for(int ph=0; ph<3; ph++){
                const __half2* row2 = (const __half2*)(src + (size_t)(53*ph+yy)*Wd);
                #pragma unroll
                for(int it=0; it<3; it++){
                    int idx = lane + it*32;
                    if(idx<80){
                        __half2 v = row2[idx];
                        int w0_ = idx*2;
                        __half hv[2] = {__low2half(v), __high2half(v)};
                        #pragma unroll
                        for(int hh=0; hh<2; hh++){
                            int w = w0_ + hh;
                            #pragma unroll
                            for(int pw=0; pw<3; pw++){
                                int xx = w - 53*pw;
                                if(xx>=0 && xx<54) rb[wp][xx*9 + ph*3 + pw] = hv[hh];
                            }
                        }
                    }
                }
            }
            __syncwarp();
            unsigned* dst = (unsigned*)(g_u3 + (size_t)n*U3IMG + (size_t)ci*A3 + (size_t)yy*486);
            const unsigned* s = (const unsigned*)rb[wp];
            #pragma unroll
            for(int it=0; it<8; it++){
                int k = lane + it*32;
                if(k < 243) dst[k] = s[k];
            }
            // Pm partial for win3 (486 | 2916 -> run never crosses a bin)
            {
                int o0 = ci*A3 + yy*486;
                int bin = o0/KHKW3;
                float ps=0.f;
                for(int i=lane;i<486;i+=32) ps += __half2float(rb[wp][i]);
                for(int off=16;off;off>>=1) ps += __shfl_xor_sync(0xffffffffu,ps,off);
                if(lane==0) atomicAdd(&g_Pm[(16 + n*9 + (bin>>6))*64 + (bin&63)], ps);
            }
            __syncwarp();
        }
    }
}

// ================ K4a: veff/beff from Pm (spatial half) ================
__global__ void __launch_bounds__(64) k4a(const float* __restrict__ spwq_w,const float* __restrict__ spwq_b,
                                          const float* __restrict__ spwv_w,const float* __restrict__ spwv_b){
    int p = blockIdx.x, t = threadIdx.x;
    float hw = (p<16) ? 25600.f : ((p<160) ? 2916.f : 1024.f);
    __shared__ float pmean[64], swq[32];
    pmean[t] = g_Pm[p*64+t]/hw;
    __syncthreads();
    if(t<32){
        float s = spwq_b[t];
        for(int c=0;c<64;c++) s += spwq_w[t*64+c]*pmean[c];
        float m=s;
        for(int off=16;off;off>>=1) m=fmaxf(m,__shfl_xor_sync(0xffffffffu,m,off));
        float e=expf(s-m), sum=e;
        for(int off=16;off;off>>=1) sum+=__shfl_xor_sync(0xffffffffu,sum,off);
        swq[t]=e/sum;
    }
    __syncthreads();
    float v=0.f;
    for(int j=0;j<32;j++) v += swq[j]*spwv_w[j*64+t];
    g_veff[p*64+t]=v;
    if(t==0){
        float b=0.f;
        for(int j=0;j<32;j++) b += swq[j]*spwv_b[j];
        g_beff[p]=b;
    }
}

// ================ K3: fused stats + s-field (win3 + win5) ================
__global__ void __launch_bounds__(256) k_statsf(const float* __restrict__ wq,
                                                const float* __restrict__ wqb){
    __shared__ __half Vs[64*130];
    __shared__ float part[4*128];
    __shared__ float part2[4*128];
    __shared__ float es[128];
    __shared__ float ve[64];
    int lin = blockIdx.x, n = blockIdx.z;
    int t = threadIdx.x;
    const __half* base; float* sf; int khkw, pi, q0;
    if(lin < 207){
        int bp = lin%9, qt = lin/9;
        khkw = KHKW3; q0 = qt*128;
        base = g_u3 + (size_t)n*U3IMG + (size_t)bp*64*KHKW3 + q0;
        sf = g_sf3 + n*A3 + bp*KHKW3;
        pi = 16 + n*9 + bp;
    } else {
        lin -= 207;
        int bp = lin%25, qt = lin/25;
        khkw = KHKW5; q0 = qt*128;
        base = g_u5 + (size_t)n*U5IMG + (size_t)bp*64*KHKW5 + q0;
        sf = g_sf5 + n*25600 + bp*1024;
        pi = 160 + n*25 + bp;
    }
    int qlim = khkw - q0; if(qlim>128) qlim=128;

    if(t<64) ve[t]=g_veff[pi*64+t];
    for(int i=t;i<4096;i+=256){
        int c=i>>6, j2=i&63;
        unsigned v = 0;
        if(j2*2 < qlim) v = *(const unsigned*)&base[(size_t)c*khkw + j2*2];
        *(unsigned*)&Vs[c*130 + j2*2] = v;
    }
    __syncthreads();
    {   // phase 1: both dots off the same Vs reads
        int j2=t&63, cg=t>>6;
        float sx=0.f, sy=0.f, vx=0.f, vy=0.f;
        #pragma unroll 8
        for(int cc=cg*16; cc<cg*16+16; cc++){
            float2 f = __half22float2(*(const __half2*)&Vs[cc*130 + j2*2]);
            float w = wq[cc], wv = ve[cc];
            sx += w*f.x;  sy += w*f.y;
            vx += wv*f.x; vy += wv*f.y;
        }
        part [cg*128 + j2*2]   = sx;
        part [cg*128 + j2*2+1] = sy;
        part2[cg*128 + j2*2]   = vx;
        part2[cg*128 + j2*2+1] = vy;
    }
    __syncthreads();
    if(t<128){
        float qd = part[t]+part[128+t]+part[256+t]+part[384+t] + wqb[0];
        float e = (t<qlim) ? expf(qd) : 0.f;
        es[t]=e;
        float z=e;
        for(int off=16;off;off>>=1) z += __shfl_xor_sync(0xffffffffu,z,off);
        if((t&31)==0) atomicAdd(&g_Z[pi], z);
        if(t<qlim){
            float sd = part2[t]+part2[128+t]+part2[256+t]+part2[384+t] + g_beff[pi];
            sf[q0 + t] = sigf(sd);
        }
    }
    __syncthreads();
    {   // phase 2: S only (Pm handled in k2)
        int c=t&63, jg=t>>6;
        float ss=0.f;
        #pragma unroll 8
        for(int j2=jg*16; j2<jg*16+16; j2++){
            float2 f = __half22float2(*(const __half2*)&Vs[c*130 + j2*2]);
            ss += f.x*es[2*j2] + f.y*es[2*j2+1];
        }
        atomicAdd(&g_S[pi*64+c], ss);
    }
}

// ================ K4b: gt from Z,S (channel half) ================
__global__ void __launch_bounds__(64) k4b(const float* __restrict__ chwv_w, const float* __restrict__ chwv_b,
                                          const float* __restrict__ chwz_w, const float* __restrict__ chwz_b,
                                          const float* __restrict__ ln_g,  const float* __restrict__ ln_b){
    int p = blockIdx.x, t = threadIdx.x;
    __shared__ float xbar[64], wz[32], red[64];

    float Zinv = 1.f/g_Z[p];
    xbar[t] = g_S[p*64+t]*Zinv;
    __syncthreads();

    if(t<32){
        float s = chwv_b[t];
        for(int c=0;c<64;c++) s += chwv_w[t*64+c]*xbar[c];
        wz[t]=s;
    }
    __syncthreads();

    float z = chwz_b[t];
    for(int j=0;j<32;j++) z += chwz_w[t*32+j]*wz[j];

    red[t]=z; __syncthreads();
    for(int s=32;s>0;s>>=1){ if(t<s) red[t]+=red[t+s]; __syncthreads(); }
    float mu = red[0]*(1.f/64.f); __syncthreads();
    float d = z-mu;
    red[t]=d*d; __syncthreads();
    for(int s=32;s>0;s>>=1){ if(t<s) red[t]+=red[t+s]; __syncthreads(); }
    float var = red[0]*(1.f/64.f);

    float zn = d*rsqrtf(var+1e-5f)*ln_g[t] + ln_b[t];
    g_gt[p*64+t] = sigf(zn);
}

// ================ K6: swizzled vsh multiplier + HMMA GEMM ================
__global__ void __launch_bounds__(256) k6(const float* __restrict__ x, float* __restrict__ out){
    __shared__ __align__(16) __half vsh[32*264];
    __shared__ float s1s[32], icntS[32];
    __shared__ int q5s[32], cp05s[32];
    __shared__ int q3s[4][32], cp03s[4][32];
    __shared__ int nsegS[32];

    int t = threadIdx.x;
    int wt = blockIdx.x, h = blockIdx.y, n = blockIdx.z;
    int w0 = wt*32;

    const __half* exg = g_ex + (size_t)n*NO*HW + (size_t)h*Wd + w0;
    for(int i=t;i<768;i+=256){
        int k=i>>2, q=(i&3)*8;
        uint4 raw = *(const uint4*)&exg[(size_t)k*HW + q];
        const __half* hp = (const __half*)&raw;
        int ks = k ^ q;
        #pragma unroll
        for(int j=0;j<8;j++) vsh[(q+j)*264 + ks] = hp[j];
    }
    const float* xp = x + (size_t)n*64*HW + (size_t)h*Wd + w0;
    for(int i=t;i<2048;i+=256){
        int c=i>>5, px=i&31;
        vsh[px*264 + ((192+c) ^ (px&24))] = __float2half(xp[(size_t)c*HW+px]);
    }
    if(t<32){
        int w = w0 + t;
        int rp5 = ((h&31)*32 + (w&31))*P5 + (h>>5)*5 + (w>>5);
        q5s[t] = rp5 & 1023; cp05s[t] = rp5 >> 10;
        int R[2], C[2];
        int nr = cover3(h, R), nc = cover3(w, C);
        nsegS[t] = nr*nc;
        icntS[t] = 1.f/(float)(nr*nc);
        for(int ri=0;ri<nr;ri++)
            for(int cj=0;cj<nc;cj++){
                int ph=R[ri], pw=C[cj];
                int rp3 = ((h-53*ph)*54 + (w-53*pw))*P3 + ph*3 + pw;
                int s = ri*nc + cj;
                cp03s[s][t] = rp3 / KHKW3;
                q3s[s][t]   = rp3 % KHKW3;
            }
    }
    __syncthreads();

    if(t<32){
        float sd = g_beff[n];
        const float* ve = &g_veff[n*64];
        int C = t&24;
        #pragma unroll
        for(int c=0;c<64;c++) sd += ve[c]*__half2float(vsh[t*264 + (c^C)]);
        s1s[t] = sigf(sd);
    }
    __syncthreads();

    {
        int lane = t&31, wp = t>>5;
        int ci0 = lane*2;
        #pragma unroll
        for(int j=0;j<12;j++){
            int idx = wp + j*8;
            int g32 = idx>>5, pix = idx&31;
            int k = (g32<<6) + ci0;
            __half2* cell = (__half2*)&vsh[pix*264 + (k ^ (pix&24))];
            float2 exv = __half22float2(*cell);
            float m0, m1;
            if(g32==0){
                float s1 = s1s[pix];
                m0 = g_gt[n*64+ci0  ] + s1;
                m1 = g_gt[n*64+ci0+1] + s1;
            } else if(g32==2){
                int q5 = q5s[pix];
                int cpv0 = cp05s[pix] + 25*ci0;
                int cpv1 = cpv0 + 25;
                int bp0=cpv0>>6, cp0=cpv0&63, bp1=cpv1>>6, cp1=cpv1&63;
                m0 = g_gt[(160+n*25+bp0)*64+cp0] + g_sf5[n*25600 + (bp0<<10) + q5];
                m1 = g_gt[(160+n*25+bp1)*64+cp1] + g_sf5[n*25600 + (bp1<<10) + q5];
            } else {
                m0 = 0.f; m1 = 0.f;
                int ns = nsegS[pix];
                #pragma unroll
                for(int s=0;s<4;s++){
                    if(s>=ns) break;
                    int q3 = q3s[s][pix];
                    int cpv0 = cp03s[s][pix] + 9*ci0;
                    int cpv1 = cpv0 + 9;
                    int bp0=cpv0>>6, cp0=cpv0&63, bp1=cpv1>>6, cp1=cpv1&63;
                    m0 += g_gt[(16+n*9+bp0)*64+cp0] + g_sf3[n*A3 + bp0*KHKW3 + q3];
                    m1 += g_gt[(16+n*9+bp1)*64+cp1] + g_sf3[n*A3 + bp1*KHKW3 + q3];
                }
                float ic = icntS[pix];
                m0 *= ic; m1 *= ic;
            }
            exv.x *= (1.f + m0);
            exv.y *= (1.f + m1);
            *cell = __floats2half2_rn(exv.x, exv.y);
        }
    }
    __syncthreads();

    int lane = t&31, w = t>>5;
    int g = lane>>2, tig = lane&3;
    int mt = w&3, nt0 = (w>>2)*2, nt1 = nt0+1;
    int ob0 = mt*16;

    float vb0 = __ldg(&g_vb[ob0+g]), vb1 = __ldg(&g_vb[ob0+g+8]);
    float c00=vb0, c01=vb0, c02=vb1, c03=vb1;
    float c10=vb0, c11=vb0, c12=vb1, c13=vb1;

    const uint4* wa = g_WhA4 + mt*512 + lane;
    int row0 = nt0*8+g, row1 = nt1*8+g;
    int C0 = row0&24, C1 = row1&24;
    const __half* b0r = &vsh[row0*264];
    const __half* b1r = &vsh[row1*264];

    #pragma unroll
    for(int kt=0;kt<16;kt++){
        uint4 a = __ldg(&wa[kt*32]);
        int x0 = (kt*16 + tig*2) ^ C0;
        int x1 = (kt*16 + tig*2) ^ C1;
        unsigned p00 = *(const unsigned*)&b0r[x0];
        unsigned p01 = *(const unsigned*)&b0r[x0^8];
        MMA16816(c00,c01,c02,c03, a, p00,p01);
        unsigned p10 = *(const unsigned*)&b1r[x1];
        unsigned p11 = *(const unsigned*)&b1r[x1^8];
        MMA16816(c10,c11,c12,c13, a, p10,p11);
    }

    float* og = out + (size_t)n*64*HW + (size_t)h*Wd + w0;
    int px0 = nt0*8 + tig*2, px1 = nt1*8 + tig*2;
    *(float2*)&og[(size_t)(ob0+g  )*HW + px0] = make_float2(c00,c01);
    *(float2*)&og[(size_t)(ob0+g+8)*HW + px0] = make_float2(c02,c03);
    *(float2*)&og[(size_t)(ob0+g  )*HW + px1] = make_float2(c10,c11);
    *(float2*)&og[(size_t)(ob0+g+8)*HW + px1] = make_float2(c12,c13);
}

// ================ launch ================
extern "C" void kernel_launch(void* const* d_in, const int* in_sizes, int n_in,
                              void* d_out, int out_size){
    const float* x      = (const float*)d_in[0];
    const float* exp_w  = (const float*)d_in[1];
    const float* exp_b  = (const float*)d_in[2];
    const float* res_w  = (const float*)d_in[3];
    const float* res_b  = (const float*)d_in[4];
    const float* fus_w  = (const float*)d_in[5];
    const float* fus_b  = (const float*)d_in[6];
    const float* chwv_w = (const float*)d_in[7];
    const float* chwv_b = (const float*)d_in[8];
    const float* chwq_w = (const float*)d_in[9];
    const float* chwq_b = (const float*)d_in[10];
    const float* chwz_w = (const float*)d_in[11];
    const float* chwz_b = (const float*)d_in[12];
    const float* ln_g   = (const float*)d_in[13];
    const float* ln_b   = (const float*)d_in[14];
    const float* spwv_w = (const float*)d_in[15];
    const float* spwv_b = (const float*)d_in[16];
    const float* spwq_w = (const float*)d_in[17];
    const float* spwq_b = (const float*)d_in[18];
    float* out = (float*)d_out;

    k_zero<<<(NPI*64+255)/256, 256>>>();
    k_wprep<<<1, 256>>>(exp_w, res_w, res_b, fus_w, fus_b);

    k1<<<dim3(Wd/32, Hh, NIMG), 256>>>(x, exp_b, chwq_w, chwq_b);

    k2<<<dim3(86, NIMG), 256>>>();

    k4a<<<NPI, 64>>>(spwq_w, spwq_b, spwv_w, spwv_b);

    k_statsf<<<dim3(407, 1, NIMG), 256>>>(chwq_w, chwq_b);

    k4b<<<NPI, 64>>>(chwv_w, chwv_b, chwz_w, chwz_b, ln_g, ln_b);

    k6<<<dim3(Wd/32, Hh, NIMG), 256>>>(x, out);
}

// round 17
// speedup vs baseline: 1.3852x; 1.1058x over previous
#include <cuda_runtime.h>
#include <cuda_fp16.h>
#include <math.h>

typedef unsigned long long u64;

#define NIMG 16
#define NO   192
#define Hh   160
#define Wd   160
#define HW   25600

#define KHKW3 2916
#define P3    9
#define A3    26244
#define U3IMG 1679616
#define KHKW5 1024
#define P5    25
#define A5    25600
#define U5IMG 1638400
#define NPI   560

// vsh additive swizzle: half-addr(pix,k) = pix*264 + k + 2*(pix>>3)
#define VSHA(pix,k) ((pix)*264 + (k) + 2*((pix)>>3))

// ---------------- scratch ----------------
__device__ __align__(16) __half g_ex[(size_t)NIMG*NO*HW];
__device__ __align__(16) __half g_u3[(size_t)NIMG*U3IMG];
__device__ __align__(16) __half g_u5[(size_t)NIMG*U5IMG];
__device__ __align__(16) float g_sf3[NIMG*P3*KHKW3];
__device__ __align__(16) float g_sf5[NIMG*P5*KHKW5];
__device__ float g_Z[NPI], g_S[NPI*64], g_Pm[NPI*64];
__device__ float g_gt[NPI*64], g_veff[NPI*64], g_beff[NPI];
__device__ __align__(16) float g_Wall[256*64];
__device__ __align__(16) uint4 g_WhA4[4*16*32];
__device__ __align__(16) uint4 g_WK1A4[12*4*32];
__device__ float g_vb[64];
__device__ __align__(16) float g_expWt[64*NO];

// ---------------- helpers ----------------
__device__ __forceinline__ float sigf(float x){ return 1.f/(1.f+expf(-x)); }
__device__ __forceinline__ int cover3(int h, int* r){
    int n=0;
    #pragma unroll
    for(int i=0;i<3;i++){ int lo=53*i; if(h>=lo && h<=lo+53) r[n++]=i; }
    return n;
}
__device__ __forceinline__ unsigned h2pack(float a, float b){
    __half2 h = __floats2half2_rn(a,b);
    return *(unsigned*)&h;
}

#define MMA16816(c0,c1,c2,c3,a,b0,b1) \
    asm volatile("mma.sync.aligned.m16n8k16.row.col.f32.f16.f16.f32 " \
        "{%0,%1,%2,%3},{%4,%5,%6,%7},{%8,%9},{%0,%1,%2,%3};" \
        : "+f"(c0),"+f"(c1),"+f"(c2),"+f"(c3) \
        : "r"((a).x),"r"((a).y),"r"((a).z),"r"((a).w),"r"(b0),"r"(b1))

// ================ K0a: zero accumulators ================
__global__ void k_zero(){
    int i = blockIdx.x*256 + threadIdx.x;
    if(i < NPI) g_Z[i]=0.f;
    if(i < NPI*64){ g_S[i]=0.f; g_Pm[i]=0.f; }
}

// ================ K0b: weight prep ================
__global__ void k_wprep(const float* __restrict__ exp_w, const float* __restrict__ res_w,
                        const float* __restrict__ res_b, const float* __restrict__ fus_w,
                        const float* __restrict__ fus_b){
    int t = threadIdx.x;
    for(int i=t;i<64*NO;i+=256){ int c=i/NO, o=i%NO; g_expWt[i]=exp_w[o*64+c]; }
    for(int i=t;i<NO*64;i+=256){
        int k=i/64, o=i%64; float s=0.f;
        for(int c=0;c<64;c++) s += fus_w[o*64+c]*res_w[c*NO+k];
        g_Wall[i]=s;
    }
    for(int i=t;i<64*64;i+=256){ int c=i/64, o=i%64; g_Wall[(192+c)*64+o]=fus_w[o*64+c]; }
    for(int o=t;o<64;o+=256){
        float s=fus_b[o];
        for(int c=0;c<64;c++) s += fus_w[o*64+c]*res_b[c];
        g_vb[o]=s;
    }
    __syncthreads();
    for(int i=t;i<2048;i+=256){
        int mt = i>>9, kt = (i>>5)&15, lane = i&31;
        int g = lane>>2, tig = lane&3;
        int k0 = kt*16, ob0 = mt*16;
        const float* W = g_Wall;
        unsigned r0 = h2pack(W[(k0+tig*2)*64+ob0+g],     W[(k0+tig*2+1)*64+ob0+g]);
        unsigned r1 = h2pack(W[(k0+tig*2)*64+ob0+g+8],   W[(k0+tig*2+1)*64+ob0+g+8]);
        unsigned r2 = h2pack(W[(k0+tig*2+8)*64+ob0+g],   W[(k0+tig*2+9)*64+ob0+g]);
        unsigned r3 = h2pack(W[(k0+tig*2+8)*64+ob0+g+8], W[(k0+tig*2+9)*64+ob0+g+8]);
        g_WhA4[i] = make_uint4(r0,r1,r2,r3);
    }
    for(int i=t;i<1536;i+=256){
        int mt = i>>7, kt = (i>>5)&3, lane = i&31;
        int g = lane>>2, tig = lane&3;
        int k0 = kt*16, ob0 = mt*16;
        const float* W = g_expWt;
        unsigned r0 = h2pack(W[(k0+tig*2)*NO+ob0+g],     W[(k0+tig*2+1)*NO+ob0+g]);
        unsigned r1 = h2pack(W[(k0+tig*2)*NO+ob0+g+8],   W[(k0+tig*2+1)*NO+ob0+g+8]);
        unsigned r2 = h2pack(W[(k0+tig*2+8)*NO+ob0+g],   W[(k0+tig*2+9)*NO+ob0+g]);
        unsigned r3 = h2pack(W[(k0+tig*2+8)*NO+ob0+g+8], W[(k0+tig*2+9)*NO+ob0+g+8]);
        g_WK1A4[i] = make_uint4(r0,r1,r2,r3);
    }
}

// ================ K1: HMMA ex = Wexp @ x + fused win1 stats ================
__global__ void __launch_bounds__(256) k1(const float* __restrict__ x,
                                          const float* __restrict__ exp_b,
                                          const float* __restrict__ wq,
                                          const float* __restrict__ wqb){
    __shared__ __align__(16) __half xh[32*72];
    __shared__ __align__(16) __half exsh[192*40];
    __shared__ float es[32];
    int t = threadIdx.x;
    int wt = blockIdx.x, h = blockIdx.y, n = blockIdx.z;
    int w0 = wt*32;

    const float* xp = x + (size_t)n*64*HW + (size_t)h*Wd + w0;
    for(int i=t;i<512;i+=256){
        int c=i>>3, p4=(i&7)*4;
        float4 v = *(const float4*)&xp[(size_t)c*HW + p4];
        xh[(p4  )*72 + c] = __float2half(v.x);
        xh[(p4+1)*72 + c] = __float2half(v.y);
        xh[(p4+2)*72 + c] = __float2half(v.z);
        xh[(p4+3)*72 + c] = __float2half(v.w);
    }
    __syncthreads();

    int lane = t&31, w = t>>5;
    int g = lane>>2, tig = lane&3;
    int mtb = (w&3)*3, nt0 = (w>>2)*2, nt1 = nt0+1;
    int px0 = nt0*8 + tig*2, px1 = nt1*8 + tig*2;

    const __half* b0base = &xh[(nt0*8+g)*72 + tig*2];
    const __half* b1base = &xh[(nt1*8+g)*72 + tig*2];
    unsigned bf0[8], bf1[8];
    #pragma unroll
    for(int kt=0;kt<4;kt++){
        bf0[kt*2  ] = *(const unsigned*)&b0base[kt*16];
        bf0[kt*2+1] = *(const unsigned*)&b0base[kt*16+8];
        bf1[kt*2  ] = *(const unsigned*)&b1base[kt*16];
        bf1[kt*2+1] = *(const unsigned*)&b1base[kt*16+8];
    }

    #pragma unroll
    for(int mi=0;mi<3;mi++){
        int mt = mtb+mi, ob0 = mt*16;
        float c00=0,c01=0,c02=0,c03=0, c10=0,c11=0,c12=0,c13=0;
        const uint4* wa = g_WK1A4 + mt*128 + lane;
        #pragma unroll
        for(int kt=0;kt<4;kt++){
            uint4 a = __ldg(&wa[kt*32]);
            MMA16816(c00,c01,c02,c03, a, bf0[kt*2],bf0[kt*2+1]);
            MMA16816(c10,c11,c12,c13, a, bf1[kt*2],bf1[kt*2+1]);
        }
        float b0 = __ldg(&exp_b[ob0+g]), b1 = __ldg(&exp_b[ob0+g+8]);
        *(unsigned*)&exsh[(ob0+g  )*40 + px0] = h2pack(c00+b0, c01+b0);
        *(unsigned*)&exsh[(ob0+g+8)*40 + px0] = h2pack(c02+b1, c03+b1);
        *(unsigned*)&exsh[(ob0+g  )*40 + px1] = h2pack(c10+b0, c11+b0);
        *(unsigned*)&exsh[(ob0+g+8)*40 + px1] = h2pack(c12+b1, c13+b1);
    }
    __syncthreads();

    __half* exg = g_ex + (size_t)n*NO*HW + (size_t)h*Wd + w0;
    for(int i=t;i<768;i+=256){
        int r=i>>2, q=(i&3)*8;
        *(uint4*)&exg[(size_t)r*HW + q] = *(const uint4*)&exsh[r*40 + q];
    }

    if(t<32){
        float qd = wqb[0];
        #pragma unroll
        for(int c=0;c<64;c++) qd += wq[c]*__half2float(exsh[c*40+t]);
        float e = expf(qd);
        es[t]=e;
        float z=e;
        for(int off=16;off;off>>=1) z += __shfl_xor_sync(0xffffffffu,z,off);
        if(t==0) atomicAdd(&g_Z[n], z);
    }
    __syncthreads();
    if(t<64){
        float Ps=0.f, Ss=0.f;
        #pragma unroll
        for(int px=0;px<32;px++){ float v=__half2float(exsh[t*40+px]); Ps+=v; Ss+=v*es[px]; }
        atomicAdd(&g_S[n*64+t], Ss);
        atomicAdd(&g_Pm[n*64+t], Ps);
    }
}

// ================ K2: fused repack + Pm accumulation ================
__global__ void __launch_bounds__(256) k2(){
    __shared__ __align__(16) __half rb[8][800];
    int n = blockIdx.y;
    int wp = threadIdx.x >> 5, lane = threadIdx.x & 31;
    if(blockIdx.x < 32){
        int y = blockIdx.x;
        for(int cit=0; cit<8; cit++){
            int ci = cit*8 + wp;
            const __half* src = g_ex + (size_t)n*NO*HW + (size_t)(128+ci)*HW;
            #pragma unroll
            for(int ph=0; ph<5; ph++){
                const __half2* row2 = (const __half2*)(src + (size_t)(ph*32+y)*Wd);
                #pragma unroll
                for(int it=0; it<3; it++){
                    int idx = lane + it*32;
                    if(idx<80){
                        __half2 v = row2[idx];
                        int w = idx*2, pw = w>>5, xx = w&31;
                        rb[wp][xx*25 + ph*5 + pw]     = __low2half(v);
                        rb[wp][(xx+1)*25 + ph*5 + pw] = __high2half(v);
                    }
                }
            }
            __syncwarp();
            uint4* dst = (uint4*)(g_u5 + (size_t)n*U5IMG + (size_t)(ci*1024 + y*32)*25);
            const uint4* s = (const uint4*)rb[wp];
            #pragma unroll
            for(int it=0; it<4; it++){
                int k = lane + it*32;
                if(k < 100) dst[k] = s[k];
            }
            {
                int o0 = ci*25600 + y*800;
                int sb = ((o0 >> 10) + 1 << 10) - o0; if(sb > 800) sb = 800;
                float s1=0.f, s2=0.f;
                for(int i=lane;i<800;i+=32){
                    float v = __half2float(rb[wp][i]);
                    if(i<sb) s1+=v; else s2+=v;
                }
                for(int off=16;off;off>>=1){
                    s1 += __shfl_xor_sync(0xffffffffu,s1,off);
                    s2 += __shfl_xor_sync(0xffffffffu,s2,off);
                }
                if(lane==0){
                    int bin = o0>>10;
                    atomicAdd(&g_Pm[(160 + n*25 + (bin>>6))*64 + (bin&63)], s1);
                    if(sb<800){
                        int b2 = bin+1;
                        atomicAdd(&g_Pm[(160 + n*25 + (b2>>6))*64 + (b2&63)], s2);
                    }
                }
            }
            __syncwarp();
        }
    } else {
        int yy = blockIdx.x - 32;
        for(int cit=0; cit<8; cit++){
            int ci = cit*8 + wp;
            const __half* src = g_ex + (size_t)n*NO*HW + (size_t)(64+ci)*HW;
            #pragma unroll
            for(int ph=0; ph<3; ph++){
                const __half2* row2 = (const __half2*)(src + (size_t)(53*ph+yy)*Wd);
                #pragma unroll
                for(int it=0; it<3; it++){
                    int idx = lane + it*32;
                    if(idx<80){
                        __half2 v = row2[idx];
                        int w0_ = idx*2;
                        __half hv[2] = {__low2half(v), __high2half(v)};
                        #pragma unroll
                        for(int hh=0; hh<2; hh++){
                            int w = w0_ + hh;
                            #pragma unroll
                            for(int pw=0; pw<3; pw++){
                                int xx = w - 53*pw;
                                if(xx>=0 && xx<54) rb[wp][xx*9 + ph*3 + pw] = hv[hh];
                            }
                        }
                    }
                }
            }
            __syncwarp();
            unsigned* dst = (unsigned*)(g_u3 + (size_t)n*U3IMG + (size_t)ci*A3 + (size_t)yy*486);
            const unsigned* s = (const unsigned*)rb[wp];
            #pragma unroll
            for(int it=0; it<8; it++){
                int k = lane + it*32;
                if(k < 243) dst[k] = s[k];
            }
            {
                int o0 = ci*A3 + yy*486;
                int bin = o0/KHKW3;
                float ps=0.f;
                for(int i=lane;i<486;i+=32) ps += __half2float(rb[wp][i]);
                for(int off=16;off;off>>=1) ps += __shfl_xor_sync(0xffffffffu,ps,off);
                if(lane==0) atomicAdd(&g_Pm[(16 + n*9 + (bin>>6))*64 + (bin&63)], ps);
            }
            __syncwarp();
        }
    }
}

// ================ K4a: veff/beff from Pm ================
__global__ void __launch_bounds__(64) k4a(const float* __restrict__ spwq_w,const float* __restrict__ spwq_b,
                                          const float* __restrict__ spwv_w,const float* __restrict__ spwv_b){
    int p = blockIdx.x, t = threadIdx.x;
    float hw = (p<16) ? 25600.f : ((p<160) ? 2916.f : 1024.f);
    __shared__ float pmean[64], swq[32];
    pmean[t] = g_Pm[p*64+t]/hw;
    __syncthreads();
    if(t<32){
        float s = spwq_b[t];
        for(int c=0;c<64;c++) s += spwq_w[t*64+c]*pmean[c];
        float m=s;
        for(int off=16;off;off>>=1) m=fmaxf(m,__shfl_xor_sync(0xffffffffu,m,off));
        float e=expf(s-m), sum=e;
        for(int off=16;off;off>>=1) sum+=__shfl_xor_sync(0xffffffffu,sum,off);
        swq[t]=e/sum;
    }
    __syncthreads();
    float v=0.f;
    for(int j=0;j<32;j++) v += swq[j]*spwv_w[j*64+t];
    g_veff[p*64+t]=v;
    if(t==0){
        float b=0.f;
        for(int j=0;j<32;j++) b += swq[j]*spwv_b[j];
        g_beff[p]=b;
    }
}

// ================ K3: fused stats + s-field ================
__global__ void __launch_bounds__(256) k_statsf(const float* __restrict__ wq,
                                                const float* __restrict__ wqb){
    __shared__ __half Vs[64*130];
    __shared__ float part[4*128];
    __shared__ float part2[4*128];
    __shared__ float es[128];
    __shared__ float ve[64];
    int lin = blockIdx.x, n = blockIdx.z;
    int t = threadIdx.x;
    const __half* base; float* sf; int khkw, pi, q0;
    if(lin < 207){
        int bp = lin%9, qt = lin/9;
        khkw = KHKW3; q0 = qt*128;
        base = g_u3 + (size_t)n*U3IMG + (size_t)bp*64*KHKW3 + q0;
        sf = g_sf3 + n*A3 + bp*KHKW3;
        pi = 16 + n*9 + bp;
    } else {
        lin -= 207;
        int bp = lin%25, qt = lin/25;
        khkw = KHKW5; q0 = qt*128;
        base = g_u5 + (size_t)n*U5IMG + (size_t)bp*64*KHKW5 + q0;
        sf = g_sf5 + n*25600 + bp*1024;
        pi = 160 + n*25 + bp;
    }
    int qlim = khkw - q0; if(qlim>128) qlim=128;

    if(t<64) ve[t]=g_veff[pi*64+t];
    for(int i=t;i<4096;i+=256){
        int c=i>>6, j2=i&63;
        unsigned v = 0;
        if(j2*2 < qlim) v = *(const unsigned*)&base[(size_t)c*khkw + j2*2];
        *(unsigned*)&Vs[c*130 + j2*2] = v;
    }
    __syncthreads();
    {
        int j2=t&63, cg=t>>6;
        float sx=0.f, sy=0.f, vx=0.f, vy=0.f;
        #pragma unroll 8
        for(int cc=cg*16; cc<cg*16+16; cc++){
            float2 f = __half22float2(*(const __half2*)&Vs[cc*130 + j2*2]);
            float w = wq[cc], wv = ve[cc];
            sx += w*f.x;  sy += w*f.y;
            vx += wv*f.x; vy += wv*f.y;
        }
        part [cg*128 + j2*2]   = sx;
        part [cg*128 + j2*2+1] = sy;
        part2[cg*128 + j2*2]   = vx;
        part2[cg*128 + j2*2+1] = vy;
    }
    __syncthreads();
    if(t<128){
        float qd = part[t]+part[128+t]+part[256+t]+part[384+t] + wqb[0];
        float e = (t<qlim) ? expf(qd) : 0.f;
        es[t]=e;
        float z=e;
        for(int off=16;off;off>>=1) z += __shfl_xor_sync(0xffffffffu,z,off);
        if((t&31)==0) atomicAdd(&g_Z[pi], z);
        if(t<qlim){
            float sd = part2[t]+part2[128+t]+part2[256+t]+part2[384+t] + g_beff[pi];
            sf[q0 + t] = sigf(sd);
        }
    }
    __syncthreads();
    {
        int c=t&63, jg=t>>6;
        float ss=0.f;
        #pragma unroll 8
        for(int j2=jg*16; j2<jg*16+16; j2++){
            float2 f = __half22float2(*(const __half2*)&Vs[c*130 + j2*2]);
            ss += f.x*es[2*j2] + f.y*es[2*j2+1];
        }
        atomicAdd(&g_S[pi*64+c], ss);
    }
}

// ================ K4b: gt from Z,S ================
__global__ void __launch_bounds__(64) k4b(const float* __restrict__ chwv_w, const float* __restrict__ chwv_b,
                                          const float* __restrict__ chwz_w, const float* __restrict__ chwz_b,
                                          const float* __restrict__ ln_g,  const float* __restrict__ ln_b){
    int p = blockIdx.x, t = threadIdx.x;
    __shared__ float xbar[64], wz[32], red[64];

    float Zinv = 1.f/g_Z[p];
    xbar[t] = g_S[p*64+t]*Zinv;
    __syncthreads();

    if(t<32){
        float s = chwv_b[t];
        for(int c=0;c<64;c++) s += chwv_w[t*64+c]*xbar[c];
        wz[t]=s;
    }
    __syncthreads();

    float z = chwz_b[t];
    for(int j=0;j<32;j++) z += chwz_w[t*32+j]*wz[j];

    red[t]=z; __syncthreads();
    for(int s=32;s>0;s>>=1){ if(t<s) red[t]+=red[t+s]; __syncthreads(); }
    float mu = red[0]*(1.f/64.f); __syncthreads();
    float d = z-mu;
    red[t]=d*d; __syncthreads();
    for(int s=32;s>0;s>>=1){ if(t<s) red[t]+=red[t+s]; __syncthreads(); }
    float var = red[0]*(1.f/64.f);

    float zn = d*rsqrtf(var+1e-5f)*ln_g[t] + ln_b[t];
    g_gt[p*64+t] = sigf(zn);
}

// ================ K6: pix-major multiplier + HMMA GEMM (additive swizzle) ================
__global__ void __launch_bounds__(256) k6(const float* __restrict__ x, float* __restrict__ out){
    __shared__ __align__(16) __half vsh[32*264 + 8];
    __shared__ float s1s[32], icntS[32];
    __shared__ int q5s[32], cp05s[32];
    __shared__ int q3s[4][32], cp03s[4][32];
    __shared__ int nsegS[32];

    int t = threadIdx.x;
    int wt = blockIdx.x, h = blockIdx.y, n = blockIdx.z;
    int w0 = wt*32;

    // ex tile -> vsh (additive swizzle scatter; (q+j)>>3 == q>>3)
    const __half* exg = g_ex + (size_t)n*NO*HW + (size_t)h*Wd + w0;
    for(int i=t;i<768;i+=256){
        int k=i>>2, q=(i&3)*8;
        uint4 raw = *(const uint4*)&exg[(size_t)k*HW + q];
        const __half* hp = (const __half*)&raw;
        __half* dbase = &vsh[q*264 + k + 2*(q>>3)];
        #pragma unroll
        for(int j=0;j<8;j++) dbase[j*264] = hp[j];
    }
    // x -> vsh rows 192..255
    const float* xp = x + (size_t)n*64*HW + (size_t)h*Wd + w0;
    for(int i=t;i<2048;i+=256){
        int c=i>>5, px=i&31;
        vsh[VSHA(px, 192+c)] = __float2half(xp[(size_t)c*HW+px]);
    }
    if(t<32){
        int w = w0 + t;
        int rp5 = ((h&31)*32 + (w&31))*P5 + (h>>5)*5 + (w>>5);
        q5s[t] = rp5 & 1023; cp05s[t] = rp5 >> 10;
        int R[2], C[2];
        int nr = cover3(h, R), nc = cover3(w, C);
        nsegS[t] = nr*nc;
        icntS[t] = 1.f/(float)(nr*nc);
        for(int ri=0;ri<nr;ri++)
            for(int cj=0;cj<nc;cj++){
                int ph=R[ri], pw=C[cj];
                int rp3 = ((h-53*ph)*54 + (w-53*pw))*P3 + ph*3 + pw;
                int s = ri*nc + cj;
                cp03s[s][t] = rp3 / KHKW3;
                q3s[s][t]   = rp3 % KHKW3;
            }
    }
    __syncthreads();

    // win1 s-field
    if(t<32){
        float sd = g_beff[n];
        const float* ve = &g_veff[n*64];
        #pragma unroll
        for(int c=0;c<64;c++) sd += ve[c]*__half2float(vsh[VSHA(t,c)]);
        s1s[t] = sigf(sd);
    }
    __syncthreads();

    // multiplier: pix-major (lane=pix, k-pair warp-uniform) -> gt loads broadcast,
    // sf loads deduped m0/m1, RMW conflict-free
    {
        int pix = t&31, w = t>>5;
        #pragma unroll
        for(int j=0;j<12;j++){
            int kp = w + j*8;              // 0..95
            int g32 = kp>>5;
            int k = kp*2;
            int ci0 = k & 63;
            __half2* cell = (__half2*)&vsh[VSHA(pix, k)];
            float2 exv = __half22float2(*cell);
            float m0, m1;
            if(g32==0){
                float s1 = s1s[pix];
                m0 = g_gt[n*64+ci0  ] + s1;
                m1 = g_gt[n*64+ci0+1] + s1;
            } else if(g32==2){
                int q5 = q5s[pix];
                int cpv0 = cp05s[pix] + 25*ci0;
                int cpv1 = cpv0 + 25;
                int bp0=cpv0>>6, cp0=cpv0&63, bp1=cpv1>>6, cp1=cpv1&63;
                float sf0 = g_sf5[n*25600 + (bp0<<10) + q5];
                float sf1 = (bp1==bp0) ? sf0 : g_sf5[n*25600 + (bp1<<10) + q5];
                m0 = g_gt[(160+n*25+bp0)*64+cp0] + sf0;
                m1 = g_gt[(160+n*25+bp1)*64+cp1] + sf1;
            } else {
                m0 = 0.f; m1 = 0.f;
                int ns = nsegS[pix];
                #pragma unroll
                for(int s=0;s<4;s++){
                    if(s>=ns) break;
                    int q3 = q3s[s][pix];
                    int cpv0 = cp03s[s][pix] + 9*ci0;
                    int cpv1 = cpv0 + 9;
                    int bp0=cpv0>>6, cp0=cpv0&63, bp1=cpv1>>6, cp1=cpv1&63;
                    float sf0 = g_sf3[n*A3 + bp0*KHKW3 + q3];
                    float sf1 = (bp1==bp0) ? sf0 : g_sf3[n*A3 + bp1*KHKW3 + q3];
                    m0 += g_gt[(16+n*9+bp0)*64+cp0] + sf0;
                    m1 += g_gt[(16+n*9+bp1)*64+cp1] + sf1;
                }
                float ic = icntS[pix];
                m0 *= ic; m1 *= ic;
            }
            exv.x *= (1.f + m0);
            exv.y *= (1.f + m1);
            *cell = __floats2half2_rn(exv.x, exv.y);
        }
    }
    __syncthreads();

    // HMMA GEMM (additive swizzle: row>>3 = nt, constant per fragment pointer)
    int lane = t&31, w = t>>5;
    int g = lane>>2, tig = lane&3;
    int mt = w&3, nt0 = (w>>2)*2, nt1 = nt0+1;
    int ob0 = mt*16;

    float vb0 = __ldg(&g_vb[ob0+g]), vb1 = __ldg(&g_vb[ob0+g+8]);
    float c00=vb0, c01=vb0, c02=vb1, c03=vb1;
    float c10=vb0, c11=vb0, c12=vb1, c13=vb1;

    const uint4* wa = g_WhA4 + mt*512 + lane;
    int row0 = nt0*8+g, row1 = nt1*8+g;
    const __half* b0r = &vsh[row0*264 + 2*nt0 + tig*2];
    const __half* b1r = &vsh[row1*264 + 2*nt1 + tig*2];

    #pragma unroll
    for(int kt=0;kt<16;kt++){
        uint4 a = __ldg(&wa[kt*32]);
        int k0 = kt*16;
        unsigned p00 = *(const unsigned*)&b0r[k0];
        unsigned p01 = *(const unsigned*)&b0r[k0+8];
        MMA16816(c00,c01,c02,c03, a, p00,p01);
        unsigned p10 = *(const unsigned*)&b1r[k0];
        unsigned p11 = *(const unsigned*)&b1r[k0+8];
        MMA16816(c10,c11,c12,c13, a, p10,p11);
    }

    float* og = out + (size_t)n*64*HW + (size_t)h*Wd + w0;
    int px0 = nt0*8 + tig*2, px1 = nt1*8 + tig*2;
    *(float2*)&og[(size_t)(ob0+g  )*HW + px0] = make_float2(c00,c01);
    *(float2*)&og[(size_t)(ob0+g+8)*HW + px0] = make_float2(c02,c03);
    *(float2*)&og[(size_t)(ob0+g  )*HW + px1] = make_float2(c10,c11);
    *(float2*)&og[(size_t)(ob0+g+8)*HW + px1] = make_float2(c12,c13);
}

// ================ launch ================
extern "C" void kernel_launch(void* const* d_in, const int* in_sizes, int n_in,
                              void* d_out, int out_size){
    const float* x      = (const float*)d_in[0];
    const float* exp_w  = (const float*)d_in[1];
    const float* exp_b  = (const float*)d_in[2];
    const float* res_w  = (const float*)d_in[3];
    const float* res_b  = (const float*)d_in[4];
    const float* fus_w  = (const float*)d_in[5];
    const float* fus_b  = (const float*)d_in[6];
    const float* chwv_w = (const float*)d_in[7];
    const float* chwv_b = (const float*)d_in[8];
    const float* chwq_w = (const float*)d_in[9];
    const float* chwq_b = (const float*)d_in[10];
    const float* chwz_w = (const float*)d_in[11];
    const float* chwz_b = (const float*)d_in[12];
    const float* ln_g   = (const float*)d_in[13];
    const float* ln_b   = (const float*)d_in[14];
    const float* spwv_w = (const float*)d_in[15];
    const float* spwv_b = (const float*)d_in[16];
    const float* spwq_w = (const float*)d_in[17];
    const float* spwq_b = (const float*)d_in[18];
    float* out = (float*)d_out;

    k_zero<<<(NPI*64+255)/256, 256>>>();
    k_wprep<<<1, 256>>>(exp_w, res_w, res_b, fus_w, fus_b);

    k1<<<dim3(Wd/32, Hh, NIMG), 256>>>(x, exp_b, chwq_w, chwq_b);

    k2<<<dim3(86, NIMG), 256>>>();

    k4a<<<NPI, 64>>>(spwq_w, spwq_b, spwv_w, spwv_b);

    k_statsf<<<dim3(407, 1, NIMG), 256>>>(chwq_w, chwq_b);

    k4b<<<NPI, 64>>>(chwv_w, chwv_b, chwz_w, chwz_b, ln_g, ln_b);

    k6<<<dim3(Wd/32, Hh, NIMG), 256>>>(x, out);
}